// round 3
// baseline (speedup 1.0000x reference)
#include <cuda_runtime.h>
#include <math.h>

// ---------------- problem constants ----------------
constexpr int B_   = 8;
constexpr int N_   = 2049;
constexpr int C_   = 768;
constexpr int H_   = 12;
constexpr int NB_  = 4;
constexpr int HD_  = 64;
constexpr int SPB_ = 512;
constexpr int M_   = B_ * N_;           // 16392 rows
constexpr int QKVDIM_ = 3 * C_;         // 2304

// ---------------- scratch (static device globals; allocation-free) --------
__device__ float g_hln [(size_t)M_ * C_];        // LN1(x)
__device__ float g_qkv [(size_t)M_ * QKVDIM_];   // qkv projections
__device__ float g_cls [B_ * C_];                // cls token (att + h row0)
__device__ float g_qkvc[B_ * QKVDIM_];           // qkv of cls token
__device__ float g_y   [(size_t)M_ * C_];        // attention output (pre-proj)
__device__ float g_x1  [(size_t)M_ * C_];        // x + attn
__device__ float g_h2  [(size_t)M_ * C_];        // LN2(x1)
__device__ float g_fc1 [(size_t)M_ * 4 * C_];    // gelu(fc1)

// ---------------- LayerNorm ----------------
__device__ __forceinline__ void ln_core(const float* __restrict__ in,
                                        const float* __restrict__ w,
                                        const float* __restrict__ b,
                                        float* __restrict__ out) {
    int row = blockIdx.x;
    int tid = threadIdx.x;
    const float* xr = in + (size_t)row * C_;
    float v0 = xr[tid], v1 = xr[tid + 256], v2 = xr[tid + 512];
    float s  = v0 + v1 + v2;
    float ss = v0 * v0 + v1 * v1 + v2 * v2;
    __shared__ float sh[16];
    #pragma unroll
    for (int o = 16; o; o >>= 1) {
        s  += __shfl_down_sync(0xffffffffu, s,  o);
        ss += __shfl_down_sync(0xffffffffu, ss, o);
    }
    int wid = tid >> 5, lane = tid & 31;
    if (lane == 0) { sh[wid] = s; sh[wid + 8] = ss; }
    __syncthreads();
    if (tid == 0) {
        float ts = 0.f, tss = 0.f;
        #pragma unroll
        for (int i = 0; i < 8; i++) { ts += sh[i]; tss += sh[i + 8]; }
        sh[0] = ts; sh[1] = tss;
    }
    __syncthreads();
    float mu   = sh[0] * (1.f / C_);
    float var  = sh[1] * (1.f / C_) - mu * mu;
    float rstd = rsqrtf(var + 1e-6f);
    float* orow = out + (size_t)row * C_;
    orow[tid]       = (v0 - mu) * rstd * w[tid]       + b[tid];
    orow[tid + 256] = (v1 - mu) * rstd * w[tid + 256] + b[tid + 256];
    orow[tid + 512] = (v2 - mu) * rstd * w[tid + 512] + b[tid + 512];
}

__global__ void ln1_kernel(const float* __restrict__ x,
                           const float* __restrict__ w,
                           const float* __restrict__ b) {
    ln_core(x, w, b, g_hln);
}
__global__ void ln2_kernel(const float* __restrict__ w,
                           const float* __restrict__ b) {
    ln_core(g_x1, w, b, g_h2);
}

// ---------------- SGEMM: C[m,n] = sum_k A[m,k]*W[n,k] (+bias)(+epi) --------
// EPI: 0 = bias only, 1 = gelu(bias+acc), 2 = bias+acc+res
template <int EPI>
__device__ __forceinline__ void gemm_core(const float* __restrict__ A,
                                          const float* __restrict__ W,
                                          const float* __restrict__ bias,
                                          const float* __restrict__ res,
                                          float* __restrict__ Cmat,
                                          int M, int Nd, int K) {
    __shared__ float As[8][128];
    __shared__ float Bs[8][128];
    int tid = threadIdx.x;
    int tx = tid & 15, ty = tid >> 4;
    int m0 = blockIdx.y * 128, n0 = blockIdx.x * 128;
    int lr = tid >> 1;            // 0..127
    int lc = (tid & 1) * 4;       // 0 or 4

    float acc[8][8];
    #pragma unroll
    for (int i = 0; i < 8; i++)
        #pragma unroll
        for (int j = 0; j < 8; j++) acc[i][j] = 0.f;

    const float* Aptr = A + (size_t)(m0 + lr) * K + lc;
    const float* Wptr = W + (size_t)(n0 + lr) * K + lc;
    bool arow_ok = (m0 + lr) < M;

    for (int kt = 0; kt < K; kt += 8) {
        float4 av = arow_ok ? *(const float4*)(Aptr + kt)
                            : make_float4(0.f, 0.f, 0.f, 0.f);
        float4 bv = *(const float4*)(Wptr + kt);
        As[lc + 0][lr] = av.x; As[lc + 1][lr] = av.y;
        As[lc + 2][lr] = av.z; As[lc + 3][lr] = av.w;
        Bs[lc + 0][lr] = bv.x; Bs[lc + 1][lr] = bv.y;
        Bs[lc + 2][lr] = bv.z; Bs[lc + 3][lr] = bv.w;
        __syncthreads();
        #pragma unroll
        for (int k = 0; k < 8; k++) {
            float a[8], bb[8];
            *(float4*)(a)      = *(const float4*)&As[k][ty * 8];
            *(float4*)(a + 4)  = *(const float4*)&As[k][ty * 8 + 4];
            *(float4*)(bb)     = *(const float4*)&Bs[k][tx * 8];
            *(float4*)(bb + 4) = *(const float4*)&Bs[k][tx * 8 + 4];
            #pragma unroll
            for (int i = 0; i < 8; i++)
                #pragma unroll
                for (int j = 0; j < 8; j++) acc[i][j] += a[i] * bb[j];
        }
        __syncthreads();
    }

    int col0 = n0 + tx * 8;
    float bi[8];
    #pragma unroll
    for (int j = 0; j < 8; j++) bi[j] = bias ? bias[col0 + j] : 0.f;

    #pragma unroll
    for (int i = 0; i < 8; i++) {
        int row = m0 + ty * 8 + i;
        if (row >= M) continue;
        float o[8];
        #pragma unroll
        for (int j = 0; j < 8; j++) {
            float v = acc[i][j] + bi[j];
            if (EPI == 1) v = 0.5f * v * (1.f + erff(v * 0.70710678118654752f));
            if (EPI == 2) v += res[(size_t)row * Nd + col0 + j];
            o[j] = v;
        }
        *(float4*)(Cmat + (size_t)row * Nd + col0)     = *(float4*)(o);
        *(float4*)(Cmat + (size_t)row * Nd + col0 + 4) = *(float4*)(o + 4);
    }
}

__global__ __launch_bounds__(256) void gemm_qkv_kernel(const float* __restrict__ W) {
    gemm_core<0>(g_hln, W, nullptr, nullptr, g_qkv, M_, QKVDIM_, C_);
}
__global__ __launch_bounds__(256) void gemm_proj_kernel(const float* __restrict__ W,
                                                        const float* __restrict__ bias,
                                                        const float* __restrict__ res) {
    gemm_core<2>(g_y, W, bias, res, g_x1, M_, C_, C_);
}
__global__ __launch_bounds__(256) void gemm_fc1_kernel(const float* __restrict__ W,
                                                       const float* __restrict__ bias) {
    gemm_core<1>(g_h2, W, bias, nullptr, g_fc1, M_, 4 * C_, C_);
}
__global__ __launch_bounds__(256) void gemm_fc2_kernel(const float* __restrict__ W,
                                                       const float* __restrict__ bias,
                                                       float* __restrict__ out) {
    gemm_core<2>(g_fc1, W, bias, g_x1, out, M_, C_, 4 * C_);
}

// ---------------- cls global attention (q[:,0] over all N keys) -----------
__global__ void cls_attn_kernel() {
    int b = blockIdx.x / H_, h = blockIdx.x % H_;
    __shared__ float qs[64];
    __shared__ float sc[N_];
    __shared__ float r8[8];
    __shared__ float oacc[4][64];
    int tid = threadIdx.x;
    const float* base = g_qkv + (size_t)b * N_ * QKVDIM_;

    if (tid < 64) qs[tid] = base[h * 64 + tid];
    __syncthreads();

    float lmax = -1e30f;
    for (int n = tid; n < N_; n += 256) {
        const float* kr = base + (size_t)n * QKVDIM_ + C_ + h * 64;
        float s = 0.f;
        #pragma unroll
        for (int d = 0; d < 64; d++) s += qs[d] * kr[d];
        s *= 0.125f;  // HD^-0.5
        sc[n] = s;
        lmax = fmaxf(lmax, s);
    }
    #pragma unroll
    for (int o = 16; o; o >>= 1)
        lmax = fmaxf(lmax, __shfl_down_sync(0xffffffffu, lmax, o));
    if ((tid & 31) == 0) r8[tid >> 5] = lmax;
    __syncthreads();
    if (tid == 0) {
        float m = r8[0];
        #pragma unroll
        for (int i = 1; i < 8; i++) m = fmaxf(m, r8[i]);
        r8[0] = m;
    }
    __syncthreads();
    float gmax = r8[0];
    __syncthreads();

    float lsum = 0.f;
    for (int n = tid; n < N_; n += 256) {
        float p = __expf(sc[n] - gmax);
        sc[n] = p;
        lsum += p;
    }
    #pragma unroll
    for (int o = 16; o; o >>= 1) lsum += __shfl_down_sync(0xffffffffu, lsum, o);
    if ((tid & 31) == 0) r8[tid >> 5] = lsum;
    __syncthreads();
    if (tid == 0) {
        float s = 0.f;
        #pragma unroll
        for (int i = 0; i < 8; i++) s += r8[i];
        r8[0] = s;
    }
    __syncthreads();
    float gsum = r8[0];

    int d = tid & 63, g = tid >> 6;
    float a = 0.f;
    for (int n = g; n < N_; n += 4)
        a += sc[n] * base[(size_t)n * QKVDIM_ + 2 * C_ + h * 64 + d];
    oacc[g][d] = a;
    __syncthreads();
    if (tid < 64) {
        float o = (oacc[0][tid] + oacc[1][tid] + oacc[2][tid] + oacc[3][tid]) / gsum;
        float val = o + g_hln[(size_t)b * N_ * C_ + h * 64 + tid];
        g_cls[b * C_ + h * 64 + tid] = val;
        g_y[(size_t)b * N_ * C_ + h * 64 + tid] = val;  // y row 0 = cls
    }
}

// ---------------- qkv of cls token: g_qkvc = g_cls @ qkv_w.T --------------
__global__ void qkvc_kernel(const float* __restrict__ qkv_w) {
    int b = blockIdx.y;
    int j = blockIdx.x * 256 + threadIdx.x;  // 0..2303
    __shared__ float cr[C_];
    for (int i = threadIdx.x; i < C_; i += 256) cr[i] = g_cls[b * C_ + i];
    __syncthreads();
    const float* wr = qkv_w + (size_t)j * C_;
    float acc = 0.f;
    #pragma unroll 4
    for (int k = 0; k < C_; k += 4) {
        float4 wv = *(const float4*)(wr + k);
        acc += wv.x * cr[k] + wv.y * cr[k + 1] + wv.z * cr[k + 2] + wv.w * cr[k + 3];
    }
    g_qkvc[b * QKVDIM_ + j] = acc;
}

// ---------------- branch local attention (flash-style, fp32) --------------
// grid: (16 q-tiles, NB, B*H). block: 256 = 32 queries x 8 lanes.
// 513 keys per branch: key 0 = cls (kc/vc), keys 1..512 = branch tokens.
// Output scattered directly with the reference's raw reinterpretation.
__global__ __launch_bounds__(256) void branch_attn_kernel() {
    int qt = blockIdx.x;
    int nb = blockIdx.y;
    int bh = blockIdx.z;
    int b = bh / H_, h = bh % H_;

    __shared__ float Qs[32][65], Ks[32][65], Vs[32][65], S[32][33];
    __shared__ float red[32][8], rmax[32], rsum[32], nmax_s[32], scale_s[32];

    int tid = threadIdx.x;
    int q = tid >> 3, lane = tid & 7;

    if (lane == 0) { rmax[q] = -1e30f; rsum[q] = 0.f; }

    for (int e = tid; e < 32 * 64; e += 256) {
        int i = e >> 6, d = e & 63;
        int tok = 1 + nb * SPB_ + qt * 32 + i;
        Qs[i][d] = g_qkv[(size_t)(b * N_ + tok) * QKVDIM_ + h * 64 + d];
    }
    float acc[8];
    #pragma unroll
    for (int dd = 0; dd < 8; dd++) acc[dd] = 0.f;
    __syncthreads();

    for (int ch = 0; ch < 17; ch++) {   // ceil(513/32)
        int kb = ch * 32;
        for (int e = tid; e < 32 * 64; e += 256) {
            int i = e >> 6, d = e & 63;
            int kg = kb + i;
            float kv = 0.f, vv = 0.f;
            if (kg == 0) {
                const float* cb = g_qkvc + b * QKVDIM_;
                kv = cb[C_ + h * 64 + d];
                vv = cb[2 * C_ + h * 64 + d];
            } else if (kg < 513) {
                int tok = 1 + nb * SPB_ + kg - 1;
                const float* row = g_qkv + (size_t)(b * N_ + tok) * QKVDIM_;
                kv = row[C_ + h * 64 + d];
                vv = row[2 * C_ + h * 64 + d];
            }
            Ks[i][d] = kv; Vs[i][d] = vv;
        }
        __syncthreads();

        int k0 = lane * 4;
        float s0 = 0.f, s1 = 0.f, s2 = 0.f, s3 = 0.f;
        #pragma unroll
        for (int d = 0; d < 64; d++) {
            float qd = Qs[q][d];
            s0 += qd * Ks[k0 + 0][d];
            s1 += qd * Ks[k0 + 1][d];
            s2 += qd * Ks[k0 + 2][d];
            s3 += qd * Ks[k0 + 3][d];
        }
        s0 *= 0.125f; s1 *= 0.125f; s2 *= 0.125f; s3 *= 0.125f;
        if (kb + k0 + 0 >= 513) s0 = -1e30f;
        if (kb + k0 + 1 >= 513) s1 = -1e30f;
        if (kb + k0 + 2 >= 513) s2 = -1e30f;
        if (kb + k0 + 3 >= 513) s3 = -1e30f;

        float lm = fmaxf(fmaxf(s0, s1), fmaxf(s2, s3));
        red[q][lane] = lm;
        __syncthreads();
        if (lane == 0) {
            float cm = red[q][0];
            #pragma unroll
            for (int l = 1; l < 8; l++) cm = fmaxf(cm, red[q][l]);
            float om = rmax[q];
            float nm = fmaxf(om, cm);
            rmax[q] = nm;
            nmax_s[q] = nm;
            scale_s[q] = __expf(om - nm);
        }
        __syncthreads();

        float nm = nmax_s[q];
        float p0 = __expf(s0 - nm), p1 = __expf(s1 - nm);
        float p2 = __expf(s2 - nm), p3 = __expf(s3 - nm);
        S[q][k0] = p0; S[q][k0 + 1] = p1; S[q][k0 + 2] = p2; S[q][k0 + 3] = p3;
        red[q][lane] = p0 + p1 + p2 + p3;
        __syncthreads();
        if (lane == 0) {
            float cs = 0.f;
            #pragma unroll
            for (int l = 0; l < 8; l++) cs += red[q][l];
            rsum[q] = rsum[q] * scale_s[q] + cs;
        }
        float scl = scale_s[q];
        int d0 = lane * 8;
        #pragma unroll
        for (int dd = 0; dd < 8; dd++) acc[dd] *= scl;
        #pragma unroll 8
        for (int kk = 0; kk < 32; kk++) {
            float p = S[q][kk];
            #pragma unroll
            for (int dd = 0; dd < 8; dd++) acc[dd] += p * Vs[kk][d0 + dd];
        }
        __syncthreads();
    }

    float inv = 1.f / rsum[q];
    int sg = qt * 32 + q;                       // query index within branch
    int flat0 = h * (SPB_ * HD_) + sg * HD_;    // raw (H,SPB,HD) flatten
    int sp = flat0 / C_;
    int c0 = flat0 - sp * C_ + lane * 8;        // 64-chunks never cross C_
    int tok = 1 + nb * SPB_ + sp;
    float* yp = g_y + (size_t)(b * N_ + tok) * C_ + c0;
    #pragma unroll
    for (int dd = 0; dd < 8; dd++) yp[dd] = acc[dd] * inv;
}

// ---------------- launcher ----------------
extern "C" void kernel_launch(void* const* d_in, const int* in_sizes, int n_in,
                              void* d_out, int out_size) {
    const float* x      = (const float*)d_in[0];
    const float* ln1_w  = (const float*)d_in[1];
    const float* ln1_b  = (const float*)d_in[2];
    const float* qkv_w  = (const float*)d_in[3];
    const float* proj_w = (const float*)d_in[4];
    const float* proj_b = (const float*)d_in[5];
    const float* ln2_w  = (const float*)d_in[6];
    const float* ln2_b  = (const float*)d_in[7];
    const float* fc1_w  = (const float*)d_in[8];
    const float* fc1_b  = (const float*)d_in[9];
    const float* fc2_w  = (const float*)d_in[10];
    const float* fc2_b  = (const float*)d_in[11];
    float* out = (float*)d_out;

    dim3 blk(256);
    int mblocks = (M_ + 127) / 128;  // 129

    // 1. LN1
    ln1_kernel<<<M_, blk>>>(x, ln1_w, ln1_b);
    // 2. qkv = hln @ qkv_w.T
    gemm_qkv_kernel<<<dim3(QKVDIM_ / 128, mblocks), blk>>>(qkv_w);
    // 3. cls global attention (+ residual h row0) -> g_cls, y row 0
    cls_attn_kernel<<<B_ * H_, blk>>>();
    // 4. qkv of cls
    qkvc_kernel<<<dim3(QKVDIM_ / 256, B_), blk>>>(qkv_w);
    // 5. branch local attention -> y rows 1..2048 (with raw-reshape scatter)
    branch_attn_kernel<<<dim3(16, NB_, B_ * H_), blk>>>();
    // 6. x1 = x + y @ proj_w.T + proj_b
    gemm_proj_kernel<<<dim3(C_ / 128, mblocks), blk>>>(proj_w, proj_b, x);
    // 7. LN2
    ln2_kernel<<<M_, blk>>>(ln2_w, ln2_b);
    // 8. fc1 + exact gelu
    gemm_fc1_kernel<<<dim3(4 * C_ / 128, mblocks), blk>>>(fc1_w, fc1_b);
    // 9. out = x1 + fc1out @ fc2_w.T + fc2_b
    gemm_fc2_kernel<<<dim3(C_ / 128, mblocks), blk>>>(fc2_w, fc2_b, out);
}

// round 4
// speedup vs baseline: 1.0017x; 1.0017x over previous
#include <cuda_runtime.h>
#include <math.h>

// ---------------- problem constants ----------------
constexpr int B_   = 8;
constexpr int N_   = 2049;
constexpr int C_   = 768;
constexpr int H_   = 12;
constexpr int NB_  = 4;
constexpr int HD_  = 64;
constexpr int SPB_ = 512;
constexpr int M_   = B_ * N_;           // 16392 rows
constexpr int QKVDIM_ = 3 * C_;         // 2304

// ---------------- scratch (static device globals; allocation-free) --------
__device__ float g_hln [(size_t)M_ * C_];        // LN1(x)
__device__ float g_qkv [(size_t)M_ * QKVDIM_];   // qkv projections
__device__ float g_cls [B_ * C_];                // cls token (att + h row0)
__device__ float g_qkvc[B_ * QKVDIM_];           // qkv of cls token
__device__ float g_y   [(size_t)M_ * C_];        // attention output (pre-proj)
__device__ float g_x1  [(size_t)M_ * C_];        // x + attn
__device__ float g_h2  [(size_t)M_ * C_];        // LN2(x1)
__device__ float g_fc1 [(size_t)M_ * 4 * C_];    // gelu(fc1)

// ---------------- LayerNorm ----------------
__device__ __forceinline__ void ln_core(const float* __restrict__ in,
                                        const float* __restrict__ w,
                                        const float* __restrict__ b,
                                        float* __restrict__ out) {
    int row = blockIdx.x;
    int tid = threadIdx.x;
    const float* xr = in + (size_t)row * C_;
    float v0 = xr[tid], v1 = xr[tid + 256], v2 = xr[tid + 512];
    float s  = v0 + v1 + v2;
    float ss = v0 * v0 + v1 * v1 + v2 * v2;
    __shared__ float sh[16];
    #pragma unroll
    for (int o = 16; o; o >>= 1) {
        s  += __shfl_down_sync(0xffffffffu, s,  o);
        ss += __shfl_down_sync(0xffffffffu, ss, o);
    }
    int wid = tid >> 5, lane = tid & 31;
    if (lane == 0) { sh[wid] = s; sh[wid + 8] = ss; }
    __syncthreads();
    if (tid == 0) {
        float ts = 0.f, tss = 0.f;
        #pragma unroll
        for (int i = 0; i < 8; i++) { ts += sh[i]; tss += sh[i + 8]; }
        sh[0] = ts; sh[1] = tss;
    }
    __syncthreads();
    float mu   = sh[0] * (1.f / C_);
    float var  = sh[1] * (1.f / C_) - mu * mu;
    float rstd = rsqrtf(var + 1e-6f);
    float* orow = out + (size_t)row * C_;
    orow[tid]       = (v0 - mu) * rstd * w[tid]       + b[tid];
    orow[tid + 256] = (v1 - mu) * rstd * w[tid + 256] + b[tid + 256];
    orow[tid + 512] = (v2 - mu) * rstd * w[tid + 512] + b[tid + 512];
}

__global__ void ln1_kernel(const float* __restrict__ x,
                           const float* __restrict__ w,
                           const float* __restrict__ b) {
    ln_core(x, w, b, g_hln);
}
__global__ void ln2_kernel(const float* __restrict__ w,
                           const float* __restrict__ b) {
    ln_core(g_x1, w, b, g_h2);
}

// ---------------- SGEMM: C[m,n] = sum_k A[m,k]*W[n,k] (+bias)(+epi) --------
// EPI: 0 = bias only, 1 = gelu(bias+acc), 2 = bias+acc+res
template <int EPI>
__device__ __forceinline__ void gemm_core(const float* __restrict__ A,
                                          const float* __restrict__ W,
                                          const float* __restrict__ bias,
                                          const float* __restrict__ res,
                                          float* __restrict__ Cmat,
                                          int M, int Nd, int K) {
    __shared__ float As[8][128];
    __shared__ float Bs[8][128];
    int tid = threadIdx.x;
    int tx = tid & 15, ty = tid >> 4;
    int m0 = blockIdx.y * 128, n0 = blockIdx.x * 128;
    int lr = tid >> 1;            // 0..127
    int lc = (tid & 1) * 4;       // 0 or 4

    float acc[8][8];
    #pragma unroll
    for (int i = 0; i < 8; i++)
        #pragma unroll
        for (int j = 0; j < 8; j++) acc[i][j] = 0.f;

    const float* Aptr = A + (size_t)(m0 + lr) * K + lc;
    const float* Wptr = W + (size_t)(n0 + lr) * K + lc;
    bool arow_ok = (m0 + lr) < M;

    for (int kt = 0; kt < K; kt += 8) {
        float4 av = arow_ok ? *(const float4*)(Aptr + kt)
                            : make_float4(0.f, 0.f, 0.f, 0.f);
        float4 bv = *(const float4*)(Wptr + kt);
        As[lc + 0][lr] = av.x; As[lc + 1][lr] = av.y;
        As[lc + 2][lr] = av.z; As[lc + 3][lr] = av.w;
        Bs[lc + 0][lr] = bv.x; Bs[lc + 1][lr] = bv.y;
        Bs[lc + 2][lr] = bv.z; Bs[lc + 3][lr] = bv.w;
        __syncthreads();
        #pragma unroll
        for (int k = 0; k < 8; k++) {
            float a[8], bb[8];
            *(float4*)(a)      = *(const float4*)&As[k][ty * 8];
            *(float4*)(a + 4)  = *(const float4*)&As[k][ty * 8 + 4];
            *(float4*)(bb)     = *(const float4*)&Bs[k][tx * 8];
            *(float4*)(bb + 4) = *(const float4*)&Bs[k][tx * 8 + 4];
            #pragma unroll
            for (int i = 0; i < 8; i++)
                #pragma unroll
                for (int j = 0; j < 8; j++) acc[i][j] += a[i] * bb[j];
        }
        __syncthreads();
    }

    int col0 = n0 + tx * 8;
    float bi[8];
    #pragma unroll
    for (int j = 0; j < 8; j++) bi[j] = bias ? bias[col0 + j] : 0.f;

    #pragma unroll
    for (int i = 0; i < 8; i++) {
        int row = m0 + ty * 8 + i;
        if (row >= M) continue;
        float o[8];
        #pragma unroll
        for (int j = 0; j < 8; j++) {
            float v = acc[i][j] + bi[j];
            if (EPI == 1) v = 0.5f * v * (1.f + erff(v * 0.70710678118654752f));
            if (EPI == 2) v += res[(size_t)row * Nd + col0 + j];
            o[j] = v;
        }
        *(float4*)(Cmat + (size_t)row * Nd + col0)     = *(float4*)(o);
        *(float4*)(Cmat + (size_t)row * Nd + col0 + 4) = *(float4*)(o + 4);
    }
}

__global__ __launch_bounds__(256) void gemm_qkv_kernel(const float* __restrict__ W) {
    gemm_core<0>(g_hln, W, nullptr, nullptr, g_qkv, M_, QKVDIM_, C_);
}
__global__ __launch_bounds__(256) void gemm_proj_kernel(const float* __restrict__ W,
                                                        const float* __restrict__ bias,
                                                        const float* __restrict__ res) {
    gemm_core<2>(g_y, W, bias, res, g_x1, M_, C_, C_);
}
__global__ __launch_bounds__(256) void gemm_fc1_kernel(const float* __restrict__ W,
                                                       const float* __restrict__ bias) {
    gemm_core<1>(g_h2, W, bias, nullptr, g_fc1, M_, 4 * C_, C_);
}
__global__ __launch_bounds__(256) void gemm_fc2_kernel(const float* __restrict__ W,
                                                       const float* __restrict__ bias,
                                                       float* __restrict__ out) {
    gemm_core<2>(g_fc1, W, bias, g_x1, out, M_, C_, 4 * C_);
}

// ---------------- cls global attention (q[:,0] over all N keys) -----------
__global__ void cls_attn_kernel() {
    int b = blockIdx.x / H_, h = blockIdx.x % H_;
    __shared__ float qs[64];
    __shared__ float sc[N_];
    __shared__ float r8[8];
    __shared__ float oacc[4][64];
    int tid = threadIdx.x;
    const float* base = g_qkv + (size_t)b * N_ * QKVDIM_;

    if (tid < 64) qs[tid] = base[h * 64 + tid];
    __syncthreads();

    float lmax = -1e30f;
    for (int n = tid; n < N_; n += 256) {
        const float* kr = base + (size_t)n * QKVDIM_ + C_ + h * 64;
        float s = 0.f;
        #pragma unroll
        for (int d = 0; d < 64; d++) s += qs[d] * kr[d];
        s *= 0.125f;  // HD^-0.5
        sc[n] = s;
        lmax = fmaxf(lmax, s);
    }
    #pragma unroll
    for (int o = 16; o; o >>= 1)
        lmax = fmaxf(lmax, __shfl_down_sync(0xffffffffu, lmax, o));
    if ((tid & 31) == 0) r8[tid >> 5] = lmax;
    __syncthreads();
    if (tid == 0) {
        float m = r8[0];
        #pragma unroll
        for (int i = 1; i < 8; i++) m = fmaxf(m, r8[i]);
        r8[0] = m;
    }
    __syncthreads();
    float gmax = r8[0];
    __syncthreads();

    float lsum = 0.f;
    for (int n = tid; n < N_; n += 256) {
        float p = __expf(sc[n] - gmax);
        sc[n] = p;
        lsum += p;
    }
    #pragma unroll
    for (int o = 16; o; o >>= 1) lsum += __shfl_down_sync(0xffffffffu, lsum, o);
    if ((tid & 31) == 0) r8[tid >> 5] = lsum;
    __syncthreads();
    if (tid == 0) {
        float s = 0.f;
        #pragma unroll
        for (int i = 0; i < 8; i++) s += r8[i];
        r8[0] = s;
    }
    __syncthreads();
    float gsum = r8[0];

    int d = tid & 63, g = tid >> 6;
    float a = 0.f;
    for (int n = g; n < N_; n += 4)
        a += sc[n] * base[(size_t)n * QKVDIM_ + 2 * C_ + h * 64 + d];
    oacc[g][d] = a;
    __syncthreads();
    if (tid < 64) {
        float o = (oacc[0][tid] + oacc[1][tid] + oacc[2][tid] + oacc[3][tid]) / gsum;
        float val = o + g_hln[(size_t)b * N_ * C_ + h * 64 + tid];
        g_cls[b * C_ + h * 64 + tid] = val;
        g_y[(size_t)b * N_ * C_ + h * 64 + tid] = val;  // y row 0 = cls
    }
}

// ---------------- qkv of cls token: g_qkvc = g_cls @ qkv_w.T --------------
__global__ void qkvc_kernel(const float* __restrict__ qkv_w) {
    int b = blockIdx.y;
    int j = blockIdx.x * 256 + threadIdx.x;  // 0..2303
    __shared__ float cr[C_];
    for (int i = threadIdx.x; i < C_; i += 256) cr[i] = g_cls[b * C_ + i];
    __syncthreads();
    const float* wr = qkv_w + (size_t)j * C_;
    float acc = 0.f;
    #pragma unroll 4
    for (int k = 0; k < C_; k += 4) {
        float4 wv = *(const float4*)(wr + k);
        acc += wv.x * cr[k] + wv.y * cr[k + 1] + wv.z * cr[k + 2] + wv.w * cr[k + 3];
    }
    g_qkvc[b * QKVDIM_ + j] = acc;
}

// ---------------- branch local attention (flash-style, fp32) --------------
// grid: (16 q-tiles, NB, B*H). block: 256 = 32 queries x 8 lanes.
// 513 keys per branch: key 0 = cls (kc/vc), keys 1..512 = branch tokens.
// Output scattered directly with the reference's raw reinterpretation.
__global__ __launch_bounds__(256) void branch_attn_kernel() {
    int qt = blockIdx.x;
    int nb = blockIdx.y;
    int bh = blockIdx.z;
    int b = bh / H_, h = bh % H_;

    __shared__ float Qs[32][65], Ks[32][65], Vs[32][65], S[32][33];
    __shared__ float red[32][8], rmax[32], rsum[32], nmax_s[32], scale_s[32];

    int tid = threadIdx.x;
    int q = tid >> 3, lane = tid & 7;

    if (lane == 0) { rmax[q] = -1e30f; rsum[q] = 0.f; }

    for (int e = tid; e < 32 * 64; e += 256) {
        int i = e >> 6, d = e & 63;
        int tok = 1 + nb * SPB_ + qt * 32 + i;
        Qs[i][d] = g_qkv[(size_t)(b * N_ + tok) * QKVDIM_ + h * 64 + d];
    }
    float acc[8];
    #pragma unroll
    for (int dd = 0; dd < 8; dd++) acc[dd] = 0.f;
    __syncthreads();

    for (int ch = 0; ch < 17; ch++) {   // ceil(513/32)
        int kb = ch * 32;
        for (int e = tid; e < 32 * 64; e += 256) {
            int i = e >> 6, d = e & 63;
            int kg = kb + i;
            float kv = 0.f, vv = 0.f;
            if (kg == 0) {
                const float* cb = g_qkvc + b * QKVDIM_;
                kv = cb[C_ + h * 64 + d];
                vv = cb[2 * C_ + h * 64 + d];
            } else if (kg < 513) {
                int tok = 1 + nb * SPB_ + kg - 1;
                const float* row = g_qkv + (size_t)(b * N_ + tok) * QKVDIM_;
                kv = row[C_ + h * 64 + d];
                vv = row[2 * C_ + h * 64 + d];
            }
            Ks[i][d] = kv; Vs[i][d] = vv;
        }
        __syncthreads();

        int k0 = lane * 4;
        float s0 = 0.f, s1 = 0.f, s2 = 0.f, s3 = 0.f;
        #pragma unroll
        for (int d = 0; d < 64; d++) {
            float qd = Qs[q][d];
            s0 += qd * Ks[k0 + 0][d];
            s1 += qd * Ks[k0 + 1][d];
            s2 += qd * Ks[k0 + 2][d];
            s3 += qd * Ks[k0 + 3][d];
        }
        s0 *= 0.125f; s1 *= 0.125f; s2 *= 0.125f; s3 *= 0.125f;
        if (kb + k0 + 0 >= 513) s0 = -1e30f;
        if (kb + k0 + 1 >= 513) s1 = -1e30f;
        if (kb + k0 + 2 >= 513) s2 = -1e30f;
        if (kb + k0 + 3 >= 513) s3 = -1e30f;

        float lm = fmaxf(fmaxf(s0, s1), fmaxf(s2, s3));
        red[q][lane] = lm;
        __syncthreads();
        if (lane == 0) {
            float cm = red[q][0];
            #pragma unroll
            for (int l = 1; l < 8; l++) cm = fmaxf(cm, red[q][l]);
            float om = rmax[q];
            float nm = fmaxf(om, cm);
            rmax[q] = nm;
            nmax_s[q] = nm;
            scale_s[q] = __expf(om - nm);
        }
        __syncthreads();

        float nm = nmax_s[q];
        float p0 = __expf(s0 - nm), p1 = __expf(s1 - nm);
        float p2 = __expf(s2 - nm), p3 = __expf(s3 - nm);
        S[q][k0] = p0; S[q][k0 + 1] = p1; S[q][k0 + 2] = p2; S[q][k0 + 3] = p3;
        red[q][lane] = p0 + p1 + p2 + p3;
        __syncthreads();
        if (lane == 0) {
            float cs = 0.f;
            #pragma unroll
            for (int l = 0; l < 8; l++) cs += red[q][l];
            rsum[q] = rsum[q] * scale_s[q] + cs;
        }
        float scl = scale_s[q];
        int d0 = lane * 8;
        #pragma unroll
        for (int dd = 0; dd < 8; dd++) acc[dd] *= scl;
        #pragma unroll 8
        for (int kk = 0; kk < 32; kk++) {
            float p = S[q][kk];
            #pragma unroll
            for (int dd = 0; dd < 8; dd++) acc[dd] += p * Vs[kk][d0 + dd];
        }
        __syncthreads();
    }

    float inv = 1.f / rsum[q];
    int sg = qt * 32 + q;                       // query index within branch
    int flat0 = h * (SPB_ * HD_) + sg * HD_;    // raw (H,SPB,HD) flatten
    int sp = flat0 / C_;
    int c0 = flat0 - sp * C_ + lane * 8;        // 64-chunks never cross C_
    int tok = 1 + nb * SPB_ + sp;
    float* yp = g_y + (size_t)(b * N_ + tok) * C_ + c0;
    #pragma unroll
    for (int dd = 0; dd < 8; dd++) yp[dd] = acc[dd] * inv;
}

// ---------------- launcher ----------------
extern "C" void kernel_launch(void* const* d_in, const int* in_sizes, int n_in,
                              void* d_out, int out_size) {
    const float* x      = (const float*)d_in[0];
    const float* ln1_w  = (const float*)d_in[1];
    const float* ln1_b  = (const float*)d_in[2];
    const float* qkv_w  = (const float*)d_in[3];
    const float* proj_w = (const float*)d_in[4];
    const float* proj_b = (const float*)d_in[5];
    const float* ln2_w  = (const float*)d_in[6];
    const float* ln2_b  = (const float*)d_in[7];
    const float* fc1_w  = (const float*)d_in[8];
    const float* fc1_b  = (const float*)d_in[9];
    const float* fc2_w  = (const float*)d_in[10];
    const float* fc2_b  = (const float*)d_in[11];
    float* out = (float*)d_out;

    dim3 blk(256);
    int mblocks = (M_ + 127) / 128;  // 129

    // 1. LN1
    ln1_kernel<<<M_, blk>>>(x, ln1_w, ln1_b);
    // 2. qkv = hln @ qkv_w.T
    gemm_qkv_kernel<<<dim3(QKVDIM_ / 128, mblocks), blk>>>(qkv_w);
    // 3. cls global attention (+ residual h row0) -> g_cls, y row 0
    cls_attn_kernel<<<B_ * H_, blk>>>();
    // 4. qkv of cls
    qkvc_kernel<<<dim3(QKVDIM_ / 256, B_), blk>>>(qkv_w);
    // 5. branch local attention -> y rows 1..2048 (with raw-reshape scatter)
    branch_attn_kernel<<<dim3(16, NB_, B_ * H_), blk>>>();
    // 6. x1 = x + y @ proj_w.T + proj_b
    gemm_proj_kernel<<<dim3(C_ / 128, mblocks), blk>>>(proj_w, proj_b, x);
    // 7. LN2
    ln2_kernel<<<M_, blk>>>(ln2_w, ln2_b);
    // 8. fc1 + exact gelu
    gemm_fc1_kernel<<<dim3(4 * C_ / 128, mblocks), blk>>>(fc1_w, fc1_b);
    // 9. out = x1 + fc1out @ fc2_w.T + fc2_b
    gemm_fc2_kernel<<<dim3(C_ / 128, mblocks), blk>>>(fc2_w, fc2_b, out);
}

// round 8
// speedup vs baseline: 1.7457x; 1.7428x over previous
#include <cuda_runtime.h>
#include <cuda_bf16.h>
#include <math.h>

// ---------------- problem constants ----------------
constexpr int B_   = 8;
constexpr int N_   = 2049;
constexpr int C_   = 768;
constexpr int H_   = 12;
constexpr int NB_  = 4;
constexpr int HD_  = 64;
constexpr int SPB_ = 512;
constexpr int M_   = B_ * N_;           // 16392
constexpr int QKVDIM_ = 3 * C_;         // 2304

// ---------------- scratch ----------------
__device__ float g_hln [(size_t)M_ * C_];
__device__ float g_qkv [(size_t)M_ * QKVDIM_];
__device__ float g_cls [B_ * C_];
__device__ float g_qkvc[B_ * QKVDIM_];
__device__ float g_y   [(size_t)M_ * C_];
__device__ float g_x1  [(size_t)M_ * C_];

__device__ __nv_bfloat16 g_hlnh[(size_t)M_ * C_],  g_hlnl[(size_t)M_ * C_];
__device__ __nv_bfloat16 g_yh  [(size_t)M_ * C_],  g_yl  [(size_t)M_ * C_];
__device__ __nv_bfloat16 g_h2h [(size_t)M_ * C_],  g_h2l [(size_t)M_ * C_];
__device__ __nv_bfloat16 g_fc1h[(size_t)M_ * 4 * C_], g_fc1l[(size_t)M_ * 4 * C_];
__device__ __nv_bfloat16 g_qwh [QKVDIM_ * C_], g_qwl [QKVDIM_ * C_];
__device__ __nv_bfloat16 g_pwh [C_ * C_],      g_pwl [C_ * C_];
__device__ __nv_bfloat16 g_f1wh[4 * C_ * C_],  g_f1wl[4 * C_ * C_];
__device__ __nv_bfloat16 g_f2wh[C_ * 4 * C_],  g_f2wl[C_ * 4 * C_];

// ---------------- PTX helpers (baseline ISA only: sm_80+) ----------------
__device__ __forceinline__ unsigned smem_u32(const void* p) {
    unsigned a;
    asm("{ .reg .u64 t; cvta.to.shared.u64 t, %1; cvt.u32.u64 %0, t; }"
        : "=r"(a) : "l"(p));
    return a;
}
#define LDSM4(d0, d1, d2, d3, addr)                                             \
    asm volatile("ldmatrix.sync.aligned.m8n8.x4.shared.b16 {%0,%1,%2,%3}, [%4];" \
        : "=r"(d0), "=r"(d1), "=r"(d2), "=r"(d3) : "r"(addr))
#define MMA16816(d, a, b)                                                       \
    asm volatile("mma.sync.aligned.m16n8k16.row.col.f32.bf16.bf16.f32 "         \
        "{%0,%1,%2,%3}, {%4,%5,%6,%7}, {%8,%9}, {%0,%1,%2,%3};"                 \
        : "+f"((d)[0]), "+f"((d)[1]), "+f"((d)[2]), "+f"((d)[3])                \
        : "r"((a)[0]), "r"((a)[1]), "r"((a)[2]), "r"((a)[3]),                   \
          "r"((b)[0]), "r"((b)[1]))
#define CP_ASYNC16(dst, src, sz)                                                \
    asm volatile("cp.async.ca.shared.global [%0], [%1], 16, %2;"                \
                 :: "r"(dst), "l"(src), "r"(sz))
#define CP_COMMIT() asm volatile("cp.async.commit_group;" ::: "memory")
#define CP_WAIT1()  asm volatile("cp.async.wait_group 1;" ::: "memory")
#define CP_WAIT0()  asm volatile("cp.async.wait_group 0;" ::: "memory")

// ---------------- LayerNorm (fp32 out + bf16 hi/lo) ----------------
__device__ __forceinline__ void ln_core(const float* __restrict__ in,
                                        const float* __restrict__ w,
                                        const float* __restrict__ b,
                                        float* __restrict__ out,
                                        __nv_bfloat16* __restrict__ oh,
                                        __nv_bfloat16* __restrict__ ol) {
    int row = blockIdx.x;
    int tid = threadIdx.x;
    const float* xr = in + (size_t)row * C_;
    float v0 = xr[tid], v1 = xr[tid + 256], v2 = xr[tid + 512];
    float s  = v0 + v1 + v2;
    float ss = v0 * v0 + v1 * v1 + v2 * v2;
    __shared__ float sh[16];
    #pragma unroll
    for (int o = 16; o; o >>= 1) {
        s  += __shfl_down_sync(0xffffffffu, s,  o);
        ss += __shfl_down_sync(0xffffffffu, ss, o);
    }
    int wid = tid >> 5, lane = tid & 31;
    if (lane == 0) { sh[wid] = s; sh[wid + 8] = ss; }
    __syncthreads();
    if (tid == 0) {
        float ts = 0.f, tss = 0.f;
        #pragma unroll
        for (int i = 0; i < 8; i++) { ts += sh[i]; tss += sh[i + 8]; }
        sh[0] = ts; sh[1] = tss;
    }
    __syncthreads();
    float mu   = sh[0] * (1.f / C_);
    float var  = sh[1] * (1.f / C_) - mu * mu;
    float rstd = rsqrtf(var + 1e-6f);
    size_t rb = (size_t)row * C_;
    #pragma unroll
    for (int p = 0; p < 3; p++) {
        int idx = tid + p * 256;
        float v = (p == 0) ? v0 : (p == 1) ? v1 : v2;
        float o = (v - mu) * rstd * w[idx] + b[idx];
        if (out) out[rb + idx] = o;
        __nv_bfloat16 h = __float2bfloat16(o);
        oh[rb + idx] = h;
        ol[rb + idx] = __float2bfloat16(o - __bfloat162float(h));
    }
}
__global__ void ln1_kernel(const float* __restrict__ x,
                           const float* __restrict__ w,
                           const float* __restrict__ b) {
    ln_core(x, w, b, g_hln, g_hlnh, g_hlnl);
}
__global__ void ln2_kernel(const float* __restrict__ w,
                           const float* __restrict__ b) {
    ln_core(g_x1, w, b, nullptr, g_h2h, g_h2l);
}

// ---------------- fp32 -> bf16 hi/lo split ----------------
__global__ void conv_kernel(const float* __restrict__ src,
                            __nv_bfloat16* __restrict__ hi,
                            __nv_bfloat16* __restrict__ lo, int n4) {
    int i = blockIdx.x * 256 + threadIdx.x;
    if (i >= n4) return;
    float4 v = ((const float4*)src)[i];
    __nv_bfloat16 h0 = __float2bfloat16(v.x), h1 = __float2bfloat16(v.y);
    __nv_bfloat16 h2 = __float2bfloat16(v.z), h3 = __float2bfloat16(v.w);
    __nv_bfloat162 hp0; hp0.x = h0; hp0.y = h1;
    __nv_bfloat162 hp1; hp1.x = h2; hp1.y = h3;
    __nv_bfloat162 lp0, lp1;
    lp0.x = __float2bfloat16(v.x - __bfloat162float(h0));
    lp0.y = __float2bfloat16(v.y - __bfloat162float(h1));
    lp1.x = __float2bfloat16(v.z - __bfloat162float(h2));
    lp1.y = __float2bfloat16(v.w - __bfloat162float(h3));
    ((__nv_bfloat162*)hi)[2 * i]     = hp0;
    ((__nv_bfloat162*)hi)[2 * i + 1] = hp1;
    ((__nv_bfloat162*)lo)[2 * i]     = lp0;
    ((__nv_bfloat162*)lo)[2 * i + 1] = lp1;
}

// ---------------- mma.sync split-bf16 GEMM ----------------
// C[m,n] = sum_k A[m,k]*W[n,k]; A,W as bf16 hi/lo pairs; fp32 accum.
// CTA tile 128x128; 8 warps as 4(m) x 2(n) -> warp tile 32x64.
// K chunks of 32, cp.async double-buffered SMEM.
// EPI: 0 = plain fp32; 1 = gelu -> bf16 hi/lo; 2 = +bias+res -> fp32
constexpr int KC_    = 32;
constexpr int LDS_   = 40;             // padded row stride (bf16 elems)
constexpr int MAT_   = 128 * LDS_;     // elems per matrix per stage
constexpr int STAGE_ = 4 * MAT_;       // Ah,Al,Bh,Bl
constexpr int TC_SMEM = 2 * STAGE_ * 2;  // bytes (81920)

template <int EPI>
__device__ __forceinline__ void tc_gemm_core(
        const __nv_bfloat16* __restrict__ Ah, const __nv_bfloat16* __restrict__ Al,
        const __nv_bfloat16* __restrict__ Bh, const __nv_bfloat16* __restrict__ Bl,
        int M, int Nd, int K,
        const float* __restrict__ bias, const float* __restrict__ res,
        float* __restrict__ Cout,
        __nv_bfloat16* __restrict__ OHi, __nv_bfloat16* __restrict__ OLo) {
    extern __shared__ __nv_bfloat16 sm[];
    int tid = threadIdx.x, warp = tid >> 5, lane = tid & 31;
    int wm = warp >> 1, wn = warp & 1;
    int m0 = blockIdx.y * 128, n0 = blockIdx.x * 128;

    float acc[2][8][4];
    #pragma unroll
    for (int i = 0; i < 2; i++)
        #pragma unroll
        for (int j = 0; j < 8; j++)
            #pragma unroll
            for (int k = 0; k < 4; k++) acc[i][j][k] = 0.f;

    auto issue_stage = [&](int stg, int kc) {
        __nv_bfloat16* sb = sm + stg * STAGE_;
        #pragma unroll
        for (int t = 0; t < 4; t++) {
            const __nv_bfloat16* src = (t == 0) ? Ah : (t == 1) ? Al
                                     : (t == 2) ? Bh : Bl;
            #pragma unroll
            for (int i = 0; i < 2; i++) {
                int idx = tid + i * 256;           // 0..511
                int r = idx >> 2, c8 = (idx & 3) * 8;
                int row = ((t < 2) ? m0 : n0) + r;
                const void* gp = src + (size_t)row * K + kc + c8;
                unsigned sp = smem_u32(sb + t * MAT_ + r * LDS_ + c8);
                int sz = (t >= 2 || row < M) ? 16 : 0;
                CP_ASYNC16(sp, gp, sz);
            }
        }
        CP_COMMIT();
    };

    issue_stage(0, 0);
    const int nch = K / KC_;

    for (int c = 0; c < nch; c++) {
        if (c + 1 < nch) { issue_stage((c + 1) & 1, (c + 1) * KC_); CP_WAIT1(); }
        else             { CP_WAIT0(); }
        __syncthreads();

        const __nv_bfloat16* sb = sm + (c & 1) * STAGE_;
        unsigned aB = smem_u32(sb + wm * 32 * LDS_);
        unsigned bB = smem_u32(sb + 2 * MAT_ + wn * 64 * LDS_);

        #pragma unroll
        for (int ks = 0; ks < 2; ks++) {
            int k = ks * 16;
            unsigned ah[2][4], al[2][4];
            #pragma unroll
            for (int mt = 0; mt < 2; mt++) {
                int lrow = mt * 16 + (lane & 15);
                int lcol = k + ((lane >> 4) << 3);
                unsigned ad = aB + (unsigned)(lrow * LDS_ + lcol) * 2u;
                LDSM4(ah[mt][0], ah[mt][1], ah[mt][2], ah[mt][3], ad);
                LDSM4(al[mt][0], al[mt][1], al[mt][2], al[mt][3], ad + MAT_ * 2u);
            }
            unsigned bh[8][2], bl[8][2];
            #pragma unroll
            for (int np = 0; np < 4; np++) {       // pairs of n8 tiles
                int r = lane & 7, tt = lane >> 3;  // tt: 0..3
                int nrow = np * 16 + ((tt >> 1) << 3) + r;
                int kcol = k + ((tt & 1) << 3);
                unsigned bd = bB + (unsigned)(nrow * LDS_ + kcol) * 2u;
                unsigned r0, r1, r2, r3;
                LDSM4(r0, r1, r2, r3, bd);
                bh[np * 2][0] = r0; bh[np * 2][1] = r1;
                bh[np * 2 + 1][0] = r2; bh[np * 2 + 1][1] = r3;
                LDSM4(r0, r1, r2, r3, bd + MAT_ * 2u);
                bl[np * 2][0] = r0; bl[np * 2][1] = r1;
                bl[np * 2 + 1][0] = r2; bl[np * 2 + 1][1] = r3;
            }
            #pragma unroll
            for (int mt = 0; mt < 2; mt++)
                #pragma unroll
                for (int nt = 0; nt < 8; nt++) {
                    MMA16816(acc[mt][nt], ah[mt], bh[nt]);
                    MMA16816(acc[mt][nt], ah[mt], bl[nt]);
                    MMA16816(acc[mt][nt], al[mt], bh[nt]);
                }
        }
        __syncthreads();
    }

    // ---- epilogue ----
    int grp = lane >> 2, tq = lane & 3;
    #pragma unroll
    for (int mt = 0; mt < 2; mt++) {
        #pragma unroll
        for (int half = 0; half < 2; half++) {     // d0,d1 vs d2,d3 (row+8)
            int row = m0 + wm * 32 + mt * 16 + grp + half * 8;
            if (row >= M) continue;
            #pragma unroll
            for (int nt = 0; nt < 8; nt++) {
                int col = n0 + wn * 64 + nt * 8 + tq * 2;
                float v0 = acc[mt][nt][half * 2];
                float v1 = acc[mt][nt][half * 2 + 1];
                if (EPI == 0) {
                    *(float2*)(Cout + (size_t)row * Nd + col) = make_float2(v0, v1);
                } else if (EPI == 2) {
                    const float2 rv = *(const float2*)(res + (size_t)row * Nd + col);
                    *(float2*)(Cout + (size_t)row * Nd + col) = make_float2(
                        v0 + bias[col] + rv.x, v1 + bias[col + 1] + rv.y);
                } else {   // gelu -> bf16 hi/lo
                    float a  = v0 + bias[col];
                    float b2 = v1 + bias[col + 1];
                    a  = 0.5f * a  * (1.f + erff(a  * 0.70710678118654752f));
                    b2 = 0.5f * b2 * (1.f + erff(b2 * 0.70710678118654752f));
                    __nv_bfloat16 ha = __float2bfloat16(a);
                    __nv_bfloat16 hb = __float2bfloat16(b2);
                    __nv_bfloat162 hp; hp.x = ha; hp.y = hb;
                    __nv_bfloat162 lp;
                    lp.x = __float2bfloat16(a  - __bfloat162float(ha));
                    lp.y = __float2bfloat16(b2 - __bfloat162float(hb));
                    size_t base = (size_t)row * Nd + col;
                    *(__nv_bfloat162*)(OHi + base) = hp;
                    *(__nv_bfloat162*)(OLo + base) = lp;
                }
            }
        }
    }
}

__global__ __launch_bounds__(256) void tc_qkv_kernel() {
    tc_gemm_core<0>(g_hlnh, g_hlnl, g_qwh, g_qwl, M_, QKVDIM_, C_,
                    nullptr, nullptr, g_qkv, nullptr, nullptr);
}
__global__ __launch_bounds__(256) void tc_proj_kernel(const float* bias,
                                                      const float* res) {
    tc_gemm_core<2>(g_yh, g_yl, g_pwh, g_pwl, M_, C_, C_,
                    bias, res, g_x1, nullptr, nullptr);
}
__global__ __launch_bounds__(256) void tc_fc1_kernel(const float* bias) {
    tc_gemm_core<1>(g_h2h, g_h2l, g_f1wh, g_f1wl, M_, 4 * C_, C_,
                    bias, nullptr, nullptr, g_fc1h, g_fc1l);
}
__global__ __launch_bounds__(256) void tc_fc2_kernel(const float* bias,
                                                     float* out) {
    tc_gemm_core<2>(g_fc1h, g_fc1l, g_f2wh, g_f2wl, M_, C_, 4 * C_,
                    bias, g_x1, out, nullptr, nullptr);
}

// ---------------- cls global attention ----------------
__global__ void cls_attn_kernel() {
    int b = blockIdx.x / H_, h = blockIdx.x % H_;
    __shared__ float qs[64];
    __shared__ float sc[N_];
    __shared__ float r8[8];
    __shared__ float oacc[4][64];
    int tid = threadIdx.x;
    const float* base = g_qkv + (size_t)b * N_ * QKVDIM_;

    if (tid < 64) qs[tid] = base[h * 64 + tid];
    __syncthreads();

    float lmax = -1e30f;
    for (int n = tid; n < N_; n += 256) {
        const float* kr = base + (size_t)n * QKVDIM_ + C_ + h * 64;
        float s = 0.f;
        #pragma unroll
        for (int d = 0; d < 64; d++) s += qs[d] * kr[d];
        s *= 0.125f;
        sc[n] = s;
        lmax = fmaxf(lmax, s);
    }
    #pragma unroll
    for (int o = 16; o; o >>= 1)
        lmax = fmaxf(lmax, __shfl_down_sync(0xffffffffu, lmax, o));
    if ((tid & 31) == 0) r8[tid >> 5] = lmax;
    __syncthreads();
    if (tid == 0) {
        float m = r8[0];
        #pragma unroll
        for (int i = 1; i < 8; i++) m = fmaxf(m, r8[i]);
        r8[0] = m;
    }
    __syncthreads();
    float gmax = r8[0];
    __syncthreads();

    float lsum = 0.f;
    for (int n = tid; n < N_; n += 256) {
        float p = __expf(sc[n] - gmax);
        sc[n] = p;
        lsum += p;
    }
    #pragma unroll
    for (int o = 16; o; o >>= 1) lsum += __shfl_down_sync(0xffffffffu, lsum, o);
    if ((tid & 31) == 0) r8[tid >> 5] = lsum;
    __syncthreads();
    if (tid == 0) {
        float s = 0.f;
        #pragma unroll
        for (int i = 0; i < 8; i++) s += r8[i];
        r8[0] = s;
    }
    __syncthreads();
    float gsum = r8[0];

    int d = tid & 63, g = tid >> 6;
    float a = 0.f;
    for (int n = g; n < N_; n += 4)
        a += sc[n] * base[(size_t)n * QKVDIM_ + 2 * C_ + h * 64 + d];
    oacc[g][d] = a;
    __syncthreads();
    if (tid < 64) {
        float o = (oacc[0][tid] + oacc[1][tid] + oacc[2][tid] + oacc[3][tid]) / gsum;
        float val = o + g_hln[(size_t)b * N_ * C_ + h * 64 + tid];
        g_cls[b * C_ + h * 64 + tid] = val;
        g_y[(size_t)b * N_ * C_ + h * 64 + tid] = val;
    }
}

// ---------------- qkv of cls token ----------------
__global__ void qkvc_kernel(const float* __restrict__ qkv_w) {
    int b = blockIdx.y;
    int j = blockIdx.x * 256 + threadIdx.x;
    __shared__ float cr[C_];
    for (int i = threadIdx.x; i < C_; i += 256) cr[i] = g_cls[b * C_ + i];
    __syncthreads();
    const float* wr = qkv_w + (size_t)j * C_;
    float acc = 0.f;
    #pragma unroll 4
    for (int k = 0; k < C_; k += 4) {
        float4 wv = *(const float4*)(wr + k);
        acc += wv.x * cr[k] + wv.y * cr[k + 1] + wv.z * cr[k + 2] + wv.w * cr[k + 3];
    }
    g_qkvc[b * QKVDIM_ + j] = acc;
}

// ---------------- branch local attention (unchanged, passing) -------------
__global__ __launch_bounds__(256) void branch_attn_kernel() {
    int qt = blockIdx.x;
    int nb = blockIdx.y;
    int bh = blockIdx.z;
    int b = bh / H_, h = bh % H_;

    __shared__ float Qs[32][65], Ks[32][65], Vs[32][65], S[32][33];
    __shared__ float red[32][8], rmax[32], rsum[32], nmax_s[32], scale_s[32];

    int tid = threadIdx.x;
    int q = tid >> 3, lane = tid & 7;

    if (lane == 0) { rmax[q] = -1e30f; rsum[q] = 0.f; }

    for (int e = tid; e < 32 * 64; e += 256) {
        int i = e >> 6, d = e & 63;
        int tok = 1 + nb * SPB_ + qt * 32 + i;
        Qs[i][d] = g_qkv[(size_t)(b * N_ + tok) * QKVDIM_ + h * 64 + d];
    }
    float acc[8];
    #pragma unroll
    for (int dd = 0; dd < 8; dd++) acc[dd] = 0.f;
    __syncthreads();

    for (int ch = 0; ch < 17; ch++) {
        int kb = ch * 32;
        for (int e = tid; e < 32 * 64; e += 256) {
            int i = e >> 6, d = e & 63;
            int kg = kb + i;
            float kv = 0.f, vv = 0.f;
            if (kg == 0) {
                const float* cb = g_qkvc + b * QKVDIM_;
                kv = cb[C_ + h * 64 + d];
                vv = cb[2 * C_ + h * 64 + d];
            } else if (kg < 513) {
                int tok = 1 + nb * SPB_ + kg - 1;
                const float* row = g_qkv + (size_t)(b * N_ + tok) * QKVDIM_;
                kv = row[C_ + h * 64 + d];
                vv = row[2 * C_ + h * 64 + d];
            }
            Ks[i][d] = kv; Vs[i][d] = vv;
        }
        __syncthreads();

        int k0 = lane * 4;
        float s0 = 0.f, s1 = 0.f, s2 = 0.f, s3 = 0.f;
        #pragma unroll
        for (int d = 0; d < 64; d++) {
            float qd = Qs[q][d];
            s0 += qd * Ks[k0 + 0][d];
            s1 += qd * Ks[k0 + 1][d];
            s2 += qd * Ks[k0 + 2][d];
            s3 += qd * Ks[k0 + 3][d];
        }
        s0 *= 0.125f; s1 *= 0.125f; s2 *= 0.125f; s3 *= 0.125f;
        if (kb + k0 + 0 >= 513) s0 = -1e30f;
        if (kb + k0 + 1 >= 513) s1 = -1e30f;
        if (kb + k0 + 2 >= 513) s2 = -1e30f;
        if (kb + k0 + 3 >= 513) s3 = -1e30f;

        float lm = fmaxf(fmaxf(s0, s1), fmaxf(s2, s3));
        red[q][lane] = lm;
        __syncthreads();
        if (lane == 0) {
            float cm = red[q][0];
            #pragma unroll
            for (int l = 1; l < 8; l++) cm = fmaxf(cm, red[q][l]);
            float om = rmax[q];
            float nm = fmaxf(om, cm);
            rmax[q] = nm;
            nmax_s[q] = nm;
            scale_s[q] = __expf(om - nm);
        }
        __syncthreads();

        float nm = nmax_s[q];
        float p0 = __expf(s0 - nm), p1 = __expf(s1 - nm);
        float p2 = __expf(s2 - nm), p3 = __expf(s3 - nm);
        S[q][k0] = p0; S[q][k0 + 1] = p1; S[q][k0 + 2] = p2; S[q][k0 + 3] = p3;
        red[q][lane] = p0 + p1 + p2 + p3;
        __syncthreads();
        if (lane == 0) {
            float cs = 0.f;
            #pragma unroll
            for (int l = 0; l < 8; l++) cs += red[q][l];
            rsum[q] = rsum[q] * scale_s[q] + cs;
        }
        float scl = scale_s[q];
        int d0 = lane * 8;
        #pragma unroll
        for (int dd = 0; dd < 8; dd++) acc[dd] *= scl;
        #pragma unroll 8
        for (int kk = 0; kk < 32; kk++) {
            float p = S[q][kk];
            #pragma unroll
            for (int dd = 0; dd < 8; dd++) acc[dd] += p * Vs[kk][d0 + dd];
        }
        __syncthreads();
    }

    float inv = 1.f / rsum[q];
    int sg = qt * 32 + q;
    int flat0 = h * (SPB_ * HD_) + sg * HD_;
    int sp = flat0 / C_;
    int c0 = flat0 - sp * C_ + lane * 8;
    int tok = 1 + nb * SPB_ + sp;
    float* yp = g_y + (size_t)(b * N_ + tok) * C_ + c0;
    #pragma unroll
    for (int dd = 0; dd < 8; dd++) yp[dd] = acc[dd] * inv;
}

// ---------------- launcher ----------------
extern "C" void kernel_launch(void* const* d_in, const int* in_sizes, int n_in,
                              void* d_out, int out_size) {
    const float* x      = (const float*)d_in[0];
    const float* ln1_w  = (const float*)d_in[1];
    const float* ln1_b  = (const float*)d_in[2];
    const float* qkv_w  = (const float*)d_in[3];
    const float* proj_w = (const float*)d_in[4];
    const float* proj_b = (const float*)d_in[5];
    const float* ln2_w  = (const float*)d_in[6];
    const float* ln2_b  = (const float*)d_in[7];
    const float* fc1_w  = (const float*)d_in[8];
    const float* fc1_b  = (const float*)d_in[9];
    const float* fc2_w  = (const float*)d_in[10];
    const float* fc2_b  = (const float*)d_in[11];
    float* out = (float*)d_out;

    cudaFuncSetAttribute(tc_qkv_kernel,  cudaFuncAttributeMaxDynamicSharedMemorySize, TC_SMEM);
    cudaFuncSetAttribute(tc_proj_kernel, cudaFuncAttributeMaxDynamicSharedMemorySize, TC_SMEM);
    cudaFuncSetAttribute(tc_fc1_kernel,  cudaFuncAttributeMaxDynamicSharedMemorySize, TC_SMEM);
    cudaFuncSetAttribute(tc_fc2_kernel,  cudaFuncAttributeMaxDynamicSharedMemorySize, TC_SMEM);

    dim3 blk(256);
    int mtiles = (M_ + 127) / 128;   // 129
    auto cgrid = [](int n) { return (n + 255) / 256; };

    __nv_bfloat16 *qwh, *qwl, *pwh, *pwl, *f1h, *f1l, *f2h, *f2l, *yh, *yl;
    cudaGetSymbolAddress((void**)&qwh, g_qwh);  cudaGetSymbolAddress((void**)&qwl, g_qwl);
    cudaGetSymbolAddress((void**)&pwh, g_pwh);  cudaGetSymbolAddress((void**)&pwl, g_pwl);
    cudaGetSymbolAddress((void**)&f1h, g_f1wh); cudaGetSymbolAddress((void**)&f1l, g_f1wl);
    cudaGetSymbolAddress((void**)&f2h, g_f2wh); cudaGetSymbolAddress((void**)&f2l, g_f2wl);
    cudaGetSymbolAddress((void**)&yh, g_yh);    cudaGetSymbolAddress((void**)&yl, g_yl);
    float* ybuf;
    cudaGetSymbolAddress((void**)&ybuf, g_y);

    // weight bf16 hi/lo splits (deterministic every call)
    conv_kernel<<<cgrid(QKVDIM_ * C_ / 4), blk>>>(qkv_w, qwh, qwl, QKVDIM_ * C_ / 4);
    conv_kernel<<<cgrid(C_ * C_ / 4), blk>>>(proj_w, pwh, pwl, C_ * C_ / 4);
    conv_kernel<<<cgrid(4 * C_ * C_ / 4), blk>>>(fc1_w, f1h, f1l, 4 * C_ * C_ / 4);
    conv_kernel<<<cgrid(4 * C_ * C_ / 4), blk>>>(fc2_w, f2h, f2l, 4 * C_ * C_ / 4);

    // 1. LN1 (fp32 + bf16 split)
    ln1_kernel<<<M_, blk>>>(x, ln1_w, ln1_b);
    // 2. qkv = hln @ qkv_w.T   (tensor cores via mma.sync)
    tc_qkv_kernel<<<dim3(QKVDIM_ / 128, mtiles), blk, TC_SMEM>>>();
    // 3-5. attention (fp32, unchanged)
    cls_attn_kernel<<<B_ * H_, blk>>>();
    qkvc_kernel<<<dim3(QKVDIM_ / 256, B_), blk>>>(qkv_w);
    branch_attn_kernel<<<dim3(16, NB_, B_ * H_), blk>>>();
    // split y for proj GEMM
    conv_kernel<<<cgrid(M_ * C_ / 4), blk>>>(ybuf, yh, yl, M_ * C_ / 4);
    // 6. x1 = x + y @ proj_w.T + proj_b
    tc_proj_kernel<<<dim3(C_ / 128, mtiles), blk, TC_SMEM>>>(proj_b, x);
    // 7. LN2 (bf16 split out)
    ln2_kernel<<<M_, blk>>>(ln2_w, ln2_b);
    // 8. fc1 + exact gelu -> bf16 split
    tc_fc1_kernel<<<dim3(4 * C_ / 128, mtiles), blk, TC_SMEM>>>(fc1_b);
    // 9. out = x1 + gelu(fc1) @ fc2_w.T + fc2_b
    tc_fc2_kernel<<<dim3(C_ / 128, mtiles), blk, TC_SMEM>>>(fc2_b, out);
}

// round 10
// speedup vs baseline: 3.1055x; 1.7790x over previous
#include <cuda_runtime.h>
#include <cuda_bf16.h>
#include <math.h>

// ---------------- problem constants ----------------
constexpr int B_   = 8;
constexpr int N_   = 2049;
constexpr int C_   = 768;
constexpr int H_   = 12;
constexpr int NB_  = 4;
constexpr int HD_  = 64;
constexpr int SPB_ = 512;
constexpr int M_   = B_ * N_;           // 16392
constexpr int QKVDIM_ = 3 * C_;         // 2304

// ---------------- scratch ----------------
__device__ float g_hln [(size_t)M_ * C_];
__device__ float g_qkv [(size_t)M_ * QKVDIM_];
__device__ float g_cls [B_ * C_];
__device__ float g_qkvc[B_ * QKVDIM_];
__device__ float g_x1  [(size_t)M_ * C_];

__device__ __nv_bfloat16 g_hlnh[(size_t)M_ * C_],  g_hlnl[(size_t)M_ * C_];
__device__ __nv_bfloat16 g_yh  [(size_t)M_ * C_],  g_yl  [(size_t)M_ * C_];
__device__ __nv_bfloat16 g_h2h [(size_t)M_ * C_],  g_h2l [(size_t)M_ * C_];
__device__ __nv_bfloat16 g_fc1h[(size_t)M_ * 4 * C_], g_fc1l[(size_t)M_ * 4 * C_];
__device__ __nv_bfloat16 g_qwh [QKVDIM_ * C_], g_qwl [QKVDIM_ * C_];
__device__ __nv_bfloat16 g_pwh [C_ * C_],      g_pwl [C_ * C_];
__device__ __nv_bfloat16 g_f1wh[4 * C_ * C_],  g_f1wl[4 * C_ * C_];
__device__ __nv_bfloat16 g_f2wh[C_ * 4 * C_],  g_f2wl[C_ * 4 * C_];

// ---------------- PTX helpers (baseline ISA only: sm_80+) ----------------
__device__ __forceinline__ unsigned smem_u32(const void* p) {
    unsigned a;
    asm("{ .reg .u64 t; cvta.to.shared.u64 t, %1; cvt.u32.u64 %0, t; }"
        : "=r"(a) : "l"(p));
    return a;
}
#define LDSM4(d0, d1, d2, d3, addr)                                             \
    asm volatile("ldmatrix.sync.aligned.m8n8.x4.shared.b16 {%0,%1,%2,%3}, [%4];" \
        : "=r"(d0), "=r"(d1), "=r"(d2), "=r"(d3) : "r"(addr))
#define LDSM4T(d0, d1, d2, d3, addr)                                            \
    asm volatile("ldmatrix.sync.aligned.m8n8.x4.trans.shared.b16 {%0,%1,%2,%3}, [%4];" \
        : "=r"(d0), "=r"(d1), "=r"(d2), "=r"(d3) : "r"(addr))
#define MMA16816(d, a, b)                                                       \
    asm volatile("mma.sync.aligned.m16n8k16.row.col.f32.bf16.bf16.f32 "         \
        "{%0,%1,%2,%3}, {%4,%5,%6,%7}, {%8,%9}, {%0,%1,%2,%3};"                 \
        : "+f"((d)[0]), "+f"((d)[1]), "+f"((d)[2]), "+f"((d)[3])                \
        : "r"((a)[0]), "r"((a)[1]), "r"((a)[2]), "r"((a)[3]),                   \
          "r"((b)[0]), "r"((b)[1]))
#define CP_ASYNC16(dst, src, sz)                                                \
    asm volatile("cp.async.ca.shared.global [%0], [%1], 16, %2;"                \
                 :: "r"(dst), "l"(src), "r"(sz))
#define CP_COMMIT() asm volatile("cp.async.commit_group;" ::: "memory")
#define CP_WAIT1()  asm volatile("cp.async.wait_group 1;" ::: "memory")
#define CP_WAIT0()  asm volatile("cp.async.wait_group 0;" ::: "memory")

// ---------------- LayerNorm (fp32 out + bf16 hi/lo) ----------------
__device__ __forceinline__ void ln_core(const float* __restrict__ in,
                                        const float* __restrict__ w,
                                        const float* __restrict__ b,
                                        float* __restrict__ out,
                                        __nv_bfloat16* __restrict__ oh,
                                        __nv_bfloat16* __restrict__ ol) {
    int row = blockIdx.x;
    int tid = threadIdx.x;
    const float* xr = in + (size_t)row * C_;
    float v0 = xr[tid], v1 = xr[tid + 256], v2 = xr[tid + 512];
    float s  = v0 + v1 + v2;
    float ss = v0 * v0 + v1 * v1 + v2 * v2;
    __shared__ float sh[16];
    #pragma unroll
    for (int o = 16; o; o >>= 1) {
        s  += __shfl_down_sync(0xffffffffu, s,  o);
        ss += __shfl_down_sync(0xffffffffu, ss, o);
    }
    int wid = tid >> 5, lane = tid & 31;
    if (lane == 0) { sh[wid] = s; sh[wid + 8] = ss; }
    __syncthreads();
    if (tid == 0) {
        float ts = 0.f, tss = 0.f;
        #pragma unroll
        for (int i = 0; i < 8; i++) { ts += sh[i]; tss += sh[i + 8]; }
        sh[0] = ts; sh[1] = tss;
    }
    __syncthreads();
    float mu   = sh[0] * (1.f / C_);
    float var  = sh[1] * (1.f / C_) - mu * mu;
    float rstd = rsqrtf(var + 1e-6f);
    size_t rb = (size_t)row * C_;
    #pragma unroll
    for (int p = 0; p < 3; p++) {
        int idx = tid + p * 256;
        float v = (p == 0) ? v0 : (p == 1) ? v1 : v2;
        float o = (v - mu) * rstd * w[idx] + b[idx];
        if (out) out[rb + idx] = o;
        __nv_bfloat16 h = __float2bfloat16(o);
        oh[rb + idx] = h;
        ol[rb + idx] = __float2bfloat16(o - __bfloat162float(h));
    }
}
__global__ void ln1_kernel(const float* __restrict__ x,
                           const float* __restrict__ w,
                           const float* __restrict__ b) {
    ln_core(x, w, b, g_hln, g_hlnh, g_hlnl);
}
__global__ void ln2_kernel(const float* __restrict__ w,
                           const float* __restrict__ b) {
    ln_core(g_x1, w, b, nullptr, g_h2h, g_h2l);
}

// ---------------- fp32 -> bf16 hi/lo split ----------------
__global__ void conv_kernel(const float* __restrict__ src,
                            __nv_bfloat16* __restrict__ hi,
                            __nv_bfloat16* __restrict__ lo, int n4) {
    int i = blockIdx.x * 256 + threadIdx.x;
    if (i >= n4) return;
    float4 v = ((const float4*)src)[i];
    __nv_bfloat16 h0 = __float2bfloat16(v.x), h1 = __float2bfloat16(v.y);
    __nv_bfloat16 h2 = __float2bfloat16(v.z), h3 = __float2bfloat16(v.w);
    __nv_bfloat162 hp0; hp0.x = h0; hp0.y = h1;
    __nv_bfloat162 hp1; hp1.x = h2; hp1.y = h3;
    __nv_bfloat162 lp0, lp1;
    lp0.x = __float2bfloat16(v.x - __bfloat162float(h0));
    lp0.y = __float2bfloat16(v.y - __bfloat162float(h1));
    lp1.x = __float2bfloat16(v.z - __bfloat162float(h2));
    lp1.y = __float2bfloat16(v.w - __bfloat162float(h3));
    ((__nv_bfloat162*)hi)[2 * i]     = hp0;
    ((__nv_bfloat162*)hi)[2 * i + 1] = hp1;
    ((__nv_bfloat162*)lo)[2 * i]     = lp0;
    ((__nv_bfloat162*)lo)[2 * i + 1] = lp1;
}

// ---------------- mma.sync split-bf16 GEMM (unchanged, passing) -----------
constexpr int KC_    = 32;
constexpr int LDS_   = 40;
constexpr int MAT_   = 128 * LDS_;
constexpr int STAGE_ = 4 * MAT_;
constexpr int TC_SMEM = 2 * STAGE_ * 2;

template <int EPI>
__device__ __forceinline__ void tc_gemm_core(
        const __nv_bfloat16* __restrict__ Ah, const __nv_bfloat16* __restrict__ Al,
        const __nv_bfloat16* __restrict__ Bh, const __nv_bfloat16* __restrict__ Bl,
        int M, int Nd, int K,
        const float* __restrict__ bias, const float* __restrict__ res,
        float* __restrict__ Cout,
        __nv_bfloat16* __restrict__ OHi, __nv_bfloat16* __restrict__ OLo) {
    extern __shared__ __nv_bfloat16 sm[];
    int tid = threadIdx.x, warp = tid >> 5, lane = tid & 31;
    int wm = warp >> 1, wn = warp & 1;
    int m0 = blockIdx.y * 128, n0 = blockIdx.x * 128;

    float acc[2][8][4];
    #pragma unroll
    for (int i = 0; i < 2; i++)
        #pragma unroll
        for (int j = 0; j < 8; j++)
            #pragma unroll
            for (int k = 0; k < 4; k++) acc[i][j][k] = 0.f;

    auto issue_stage = [&](int stg, int kc) {
        __nv_bfloat16* sb = sm + stg * STAGE_;
        #pragma unroll
        for (int t = 0; t < 4; t++) {
            const __nv_bfloat16* src = (t == 0) ? Ah : (t == 1) ? Al
                                     : (t == 2) ? Bh : Bl;
            #pragma unroll
            for (int i = 0; i < 2; i++) {
                int idx = tid + i * 256;
                int r = idx >> 2, c8 = (idx & 3) * 8;
                int row = ((t < 2) ? m0 : n0) + r;
                const void* gp = src + (size_t)row * K + kc + c8;
                unsigned sp = smem_u32(sb + t * MAT_ + r * LDS_ + c8);
                int sz = (t >= 2 || row < M) ? 16 : 0;
                CP_ASYNC16(sp, gp, sz);
            }
        }
        CP_COMMIT();
    };

    issue_stage(0, 0);
    const int nch = K / KC_;

    for (int c = 0; c < nch; c++) {
        if (c + 1 < nch) { issue_stage((c + 1) & 1, (c + 1) * KC_); CP_WAIT1(); }
        else             { CP_WAIT0(); }
        __syncthreads();

        const __nv_bfloat16* sb = sm + (c & 1) * STAGE_;
        unsigned aB = smem_u32(sb + wm * 32 * LDS_);
        unsigned bB = smem_u32(sb + 2 * MAT_ + wn * 64 * LDS_);

        #pragma unroll
        for (int ks = 0; ks < 2; ks++) {
            int k = ks * 16;
            unsigned ah[2][4], al[2][4];
            #pragma unroll
            for (int mt = 0; mt < 2; mt++) {
                int lrow = mt * 16 + (lane & 15);
                int lcol = k + ((lane >> 4) << 3);
                unsigned ad = aB + (unsigned)(lrow * LDS_ + lcol) * 2u;
                LDSM4(ah[mt][0], ah[mt][1], ah[mt][2], ah[mt][3], ad);
                LDSM4(al[mt][0], al[mt][1], al[mt][2], al[mt][3], ad + MAT_ * 2u);
            }
            unsigned bh[8][2], bl[8][2];
            #pragma unroll
            for (int np = 0; np < 4; np++) {
                int r = lane & 7, tt = lane >> 3;
                int nrow = np * 16 + ((tt >> 1) << 3) + r;
                int kcol = k + ((tt & 1) << 3);
                unsigned bd = bB + (unsigned)(nrow * LDS_ + kcol) * 2u;
                unsigned r0, r1, r2, r3;
                LDSM4(r0, r1, r2, r3, bd);
                bh[np * 2][0] = r0; bh[np * 2][1] = r1;
                bh[np * 2 + 1][0] = r2; bh[np * 2 + 1][1] = r3;
                LDSM4(r0, r1, r2, r3, bd + MAT_ * 2u);
                bl[np * 2][0] = r0; bl[np * 2][1] = r1;
                bl[np * 2 + 1][0] = r2; bl[np * 2 + 1][1] = r3;
            }
            #pragma unroll
            for (int mt = 0; mt < 2; mt++)
                #pragma unroll
                for (int nt = 0; nt < 8; nt++) {
                    MMA16816(acc[mt][nt], ah[mt], bh[nt]);
                    MMA16816(acc[mt][nt], ah[mt], bl[nt]);
                    MMA16816(acc[mt][nt], al[mt], bh[nt]);
                }
        }
        __syncthreads();
    }

    int grp = lane >> 2, tq = lane & 3;
    #pragma unroll
    for (int mt = 0; mt < 2; mt++) {
        #pragma unroll
        for (int half = 0; half < 2; half++) {
            int row = m0 + wm * 32 + mt * 16 + grp + half * 8;
            if (row >= M) continue;
            #pragma unroll
            for (int nt = 0; nt < 8; nt++) {
                int col = n0 + wn * 64 + nt * 8 + tq * 2;
                float v0 = acc[mt][nt][half * 2];
                float v1 = acc[mt][nt][half * 2 + 1];
                if (EPI == 0) {
                    *(float2*)(Cout + (size_t)row * Nd + col) = make_float2(v0, v1);
                } else if (EPI == 2) {
                    const float2 rv = *(const float2*)(res + (size_t)row * Nd + col);
                    *(float2*)(Cout + (size_t)row * Nd + col) = make_float2(
                        v0 + bias[col] + rv.x, v1 + bias[col + 1] + rv.y);
                } else {
                    float a  = v0 + bias[col];
                    float b2 = v1 + bias[col + 1];
                    a  = 0.5f * a  * (1.f + erff(a  * 0.70710678118654752f));
                    b2 = 0.5f * b2 * (1.f + erff(b2 * 0.70710678118654752f));
                    __nv_bfloat16 ha = __float2bfloat16(a);
                    __nv_bfloat16 hb = __float2bfloat16(b2);
                    __nv_bfloat162 hp; hp.x = ha; hp.y = hb;
                    __nv_bfloat162 lp;
                    lp.x = __float2bfloat16(a  - __bfloat162float(ha));
                    lp.y = __float2bfloat16(b2 - __bfloat162float(hb));
                    size_t base = (size_t)row * Nd + col;
                    *(__nv_bfloat162*)(OHi + base) = hp;
                    *(__nv_bfloat162*)(OLo + base) = lp;
                }
            }
        }
    }
}

__global__ __launch_bounds__(256) void tc_qkv_kernel() {
    tc_gemm_core<0>(g_hlnh, g_hlnl, g_qwh, g_qwl, M_, QKVDIM_, C_,
                    nullptr, nullptr, g_qkv, nullptr, nullptr);
}
__global__ __launch_bounds__(256) void tc_proj_kernel(const float* bias,
                                                      const float* res) {
    tc_gemm_core<2>(g_yh, g_yl, g_pwh, g_pwl, M_, C_, C_,
                    bias, res, g_x1, nullptr, nullptr);
}
__global__ __launch_bounds__(256) void tc_fc1_kernel(const float* bias) {
    tc_gemm_core<1>(g_h2h, g_h2l, g_f1wh, g_f1wl, M_, 4 * C_, C_,
                    bias, nullptr, nullptr, g_fc1h, g_fc1l);
}
__global__ __launch_bounds__(256) void tc_fc2_kernel(const float* bias,
                                                     float* out) {
    tc_gemm_core<2>(g_fc1h, g_fc1l, g_f2wh, g_f2wl, M_, C_, 4 * C_,
                    bias, g_x1, out, nullptr, nullptr);
}

// ---------------- cls global attention (writes y row0 as bf16 split) ------
__global__ void cls_attn_kernel() {
    int b = blockIdx.x / H_, h = blockIdx.x % H_;
    __shared__ float qs[64];
    __shared__ float sc[N_];
    __shared__ float r8[8];
    __shared__ float oacc[4][64];
    int tid = threadIdx.x;
    const float* base = g_qkv + (size_t)b * N_ * QKVDIM_;

    if (tid < 64) qs[tid] = base[h * 64 + tid];
    __syncthreads();

    float lmax = -1e30f;
    for (int n = tid; n < N_; n += 256) {
        const float* kr = base + (size_t)n * QKVDIM_ + C_ + h * 64;
        float s = 0.f;
        #pragma unroll
        for (int d = 0; d < 64; d++) s += qs[d] * kr[d];
        s *= 0.125f;
        sc[n] = s;
        lmax = fmaxf(lmax, s);
    }
    #pragma unroll
    for (int o = 16; o; o >>= 1)
        lmax = fmaxf(lmax, __shfl_down_sync(0xffffffffu, lmax, o));
    if ((tid & 31) == 0) r8[tid >> 5] = lmax;
    __syncthreads();
    if (tid == 0) {
        float m = r8[0];
        #pragma unroll
        for (int i = 1; i < 8; i++) m = fmaxf(m, r8[i]);
        r8[0] = m;
    }
    __syncthreads();
    float gmax = r8[0];
    __syncthreads();

    float lsum = 0.f;
    for (int n = tid; n < N_; n += 256) {
        float p = __expf(sc[n] - gmax);
        sc[n] = p;
        lsum += p;
    }
    #pragma unroll
    for (int o = 16; o; o >>= 1) lsum += __shfl_down_sync(0xffffffffu, lsum, o);
    if ((tid & 31) == 0) r8[tid >> 5] = lsum;
    __syncthreads();
    if (tid == 0) {
        float s = 0.f;
        #pragma unroll
        for (int i = 0; i < 8; i++) s += r8[i];
        r8[0] = s;
    }
    __syncthreads();
    float gsum = r8[0];

    int d = tid & 63, g = tid >> 6;
    float a = 0.f;
    for (int n = g; n < N_; n += 4)
        a += sc[n] * base[(size_t)n * QKVDIM_ + 2 * C_ + h * 64 + d];
    oacc[g][d] = a;
    __syncthreads();
    if (tid < 64) {
        float o = (oacc[0][tid] + oacc[1][tid] + oacc[2][tid] + oacc[3][tid]) / gsum;
        float val = o + g_hln[(size_t)b * N_ * C_ + h * 64 + tid];
        g_cls[b * C_ + h * 64 + tid] = val;
        size_t yi = (size_t)b * N_ * C_ + h * 64 + tid;   // y row 0
        __nv_bfloat16 hh = __float2bfloat16(val);
        g_yh[yi] = hh;
        g_yl[yi] = __float2bfloat16(val - __bfloat162float(hh));
    }
}

// ---------------- qkv of cls token ----------------
__global__ void qkvc_kernel(const float* __restrict__ qkv_w) {
    int b = blockIdx.y;
    int j = blockIdx.x * 256 + threadIdx.x;
    __shared__ float cr[C_];
    for (int i = threadIdx.x; i < C_; i += 256) cr[i] = g_cls[b * C_ + i];
    __syncthreads();
    const float* wr = qkv_w + (size_t)j * C_;
    float acc = 0.f;
    #pragma unroll 4
    for (int k = 0; k < C_; k += 4) {
        float4 wv = *(const float4*)(wr + k);
        acc += wv.x * cr[k] + wv.y * cr[k + 1] + wv.z * cr[k + 2] + wv.w * cr[k + 3];
    }
    g_qkvc[b * QKVDIM_ + j] = acc;
}

// ---------------- branch local attention — tensor cores -------------------
// Grid: (8 qtiles of 64 queries, NB, B*H). Block 256 = 8 warps (4m x 2n).
// cls key folded into online-softmax init; 512 token keys = 8 chunks of 64.
// S = Q*K^T via 3-term bf16 split; P*V via 3-term split with ldmatrix.trans.
constexpr int ATT_SMEM = 74752;

__global__ __launch_bounds__(256) void battn_tc_kernel() {
    extern __shared__ char sm8[];
    __nv_bfloat16* Qh = (__nv_bfloat16*)(sm8);            // 64x72 bf16
    __nv_bfloat16* Ql = (__nv_bfloat16*)(sm8 + 9216);
    __nv_bfloat16* Kh = (__nv_bfloat16*)(sm8 + 18432);
    __nv_bfloat16* Kl = (__nv_bfloat16*)(sm8 + 27648);
    __nv_bfloat16* Vh = (__nv_bfloat16*)(sm8 + 36864);
    __nv_bfloat16* Ph = (__nv_bfloat16*)(sm8 + 55296);
    float* Ss   = (float*)(sm8);                          // overlays Q (64x68 f32)
    float* Vc   = (float*)(sm8 + 73728);
    float* rmax = (float*)(sm8 + 73984);
    float* rsum = (float*)(sm8 + 74240);
    float* scl  = (float*)(sm8 + 74496);

    int qt = blockIdx.x, nb = blockIdx.y, bh = blockIdx.z;
    int b = bh / H_, h = bh % H_;
    int tid = threadIdx.x, warp = tid >> 5, lane = tid & 31;
    int wm = warp >> 1, wn = warp & 1;
    int grp = lane >> 2, tq = lane & 3;

    // ---- prologue: Q (pre-scaled by 2^-3, exact) + cls k/v ----
    const size_t qbase = (size_t)(b * N_ + 1 + nb * SPB_ + qt * 64) * QKVDIM_ + h * 64;
    for (int e = tid; e < 4096; e += 256) {
        int r = e >> 6, d = e & 63;
        float qv = g_qkv[qbase + (size_t)r * QKVDIM_ + d] * 0.125f;
        __nv_bfloat16 hh = __float2bfloat16(qv);
        Qh[r * 72 + d] = hh;
        Ql[r * 72 + d] = __float2bfloat16(qv - __bfloat162float(hh));
    }
    if (tid < 64) Vc[tid] = g_qkvc[b * QKVDIM_ + 2 * C_ + h * 64 + tid];
    __syncthreads();

    // s_cls per query; init online stats
    {
        int r = tid >> 2, l4 = tid & 3;
        const float* kc = g_qkvc + b * QKVDIM_ + C_ + h * 64;
        float s = 0.f;
        #pragma unroll
        for (int j = 0; j < 16; j++) {
            int d = l4 * 16 + j;
            float qv = __bfloat162float(Qh[r * 72 + d]) + __bfloat162float(Ql[r * 72 + d]);
            s += qv * kc[d];
        }
        s += __shfl_xor_sync(0xffffffffu, s, 1);
        s += __shfl_xor_sync(0xffffffffu, s, 2);
        if (l4 == 0) { rmax[r] = s; rsum[r] = 1.f; }
    }

    // Q fragments (persistent): 4 k-steps, hi+lo
    unsigned qh[4][4], ql[4][4];
    {
        int lrow = wm * 16 + (lane & 15);
        int lcol8 = (lane >> 4) << 3;
        #pragma unroll
        for (int ks = 0; ks < 4; ks++) {
            unsigned ad = smem_u32(Qh + lrow * 72 + ks * 16 + lcol8);
            LDSM4(qh[ks][0], qh[ks][1], qh[ks][2], qh[ks][3], ad);
            LDSM4(ql[ks][0], ql[ks][1], ql[ks][2], ql[ks][3], ad + 9216u);
        }
    }

    // acc init = cls contribution (p=1 at m=s_cls)
    float pacc[4][4];
    #pragma unroll
    for (int nt = 0; nt < 4; nt++) {
        int col = wn * 32 + nt * 8 + tq * 2;
        pacc[nt][0] = Vc[col]; pacc[nt][1] = Vc[col + 1];
        pacc[nt][2] = Vc[col]; pacc[nt][3] = Vc[col + 1];
    }
    __syncthreads();   // Q frags in regs; stats visible; Ss may overlay Q

    const size_t kvbase = (size_t)(b * N_ + 1 + nb * SPB_) * QKVDIM_ + h * 64;

    for (int ch = 0; ch < 8; ch++) {
        // [A] load + split K,V chunk (64 keys x 64 dims)
        for (int e = tid; e < 4096; e += 256) {
            int i = e >> 6, d = e & 63;
            size_t rowb = kvbase + (size_t)(ch * 64 + i) * QKVDIM_;
            float kv = g_qkv[rowb + C_ + d];
            float vv = g_qkv[rowb + 2 * C_ + d];
            __nv_bfloat16 khh = __float2bfloat16(kv);
            __nv_bfloat16 vhh = __float2bfloat16(vv);
            Kh[i * 72 + d] = khh;
            Kl[i * 72 + d] = __float2bfloat16(kv - __bfloat162float(khh));
            Vh[i * 72 + d] = vhh;
            Vh[4608 + i * 72 + d] = __float2bfloat16(vv - __bfloat162float(vhh));
        }
        __syncthreads();

        // [B] S = Q*K^T (warp m16 x n32 x k64, 3-term split)
        float sacc[4][4];
        #pragma unroll
        for (int nt = 0; nt < 4; nt++)
            #pragma unroll
            for (int e = 0; e < 4; e++) sacc[nt][e] = 0.f;
        {
            int r = lane & 7, tt = lane >> 3;
            #pragma unroll
            for (int ks = 0; ks < 4; ks++) {
                unsigned kb[4][2], klo[4][2];
                #pragma unroll
                for (int np = 0; np < 2; np++) {
                    int nrow = wn * 32 + np * 16 + ((tt >> 1) << 3) + r;
                    int kcol = ks * 16 + ((tt & 1) << 3);
                    unsigned ad = smem_u32(Kh + nrow * 72 + kcol);
                    unsigned r0, r1, r2, r3;
                    LDSM4(r0, r1, r2, r3, ad);
                    kb[np * 2][0] = r0; kb[np * 2][1] = r1;
                    kb[np * 2 + 1][0] = r2; kb[np * 2 + 1][1] = r3;
                    LDSM4(r0, r1, r2, r3, ad + 9216u);
                    klo[np * 2][0] = r0; klo[np * 2][1] = r1;
                    klo[np * 2 + 1][0] = r2; klo[np * 2 + 1][1] = r3;
                }
                #pragma unroll
                for (int nt = 0; nt < 4; nt++) {
                    MMA16816(sacc[nt], qh[ks], kb[nt]);
                    MMA16816(sacc[nt], qh[ks], klo[nt]);
                    MMA16816(sacc[nt], ql[ks], kb[nt]);
                }
            }
        }
        #pragma unroll
        for (int nt = 0; nt < 4; nt++) {
            int col = wn * 32 + nt * 8 + tq * 2;
            *(float2*)&Ss[(wm * 16 + grp) * 68 + col]     = make_float2(sacc[nt][0], sacc[nt][1]);
            *(float2*)&Ss[(wm * 16 + grp + 8) * 68 + col] = make_float2(sacc[nt][2], sacc[nt][3]);
        }
        __syncthreads();

        // [C] online softmax on Ss (4 lanes per row), emit P hi/lo
        {
            int r = tid >> 2, l4 = tid & 3;
            float vals[16];
            float lm = -1e30f;
            const float* sr = &Ss[r * 68 + l4 * 16];
            #pragma unroll
            for (int j = 0; j < 16; j++) { vals[j] = sr[j]; lm = fmaxf(lm, vals[j]); }
            lm = fmaxf(lm, __shfl_xor_sync(0xffffffffu, lm, 1));
            lm = fmaxf(lm, __shfl_xor_sync(0xffffffffu, lm, 2));
            float om = rmax[r];
            float nm = fmaxf(om, lm);
            float sc = __expf(om - nm);
            float ls = 0.f;
            __nv_bfloat16* pr = Ph + r * 72 + l4 * 16;
            #pragma unroll
            for (int j = 0; j < 16; j++) {
                float p = __expf(vals[j] - nm);
                __nv_bfloat16 phh = __float2bfloat16(p);
                pr[j]        = phh;
                pr[4608 + j] = __float2bfloat16(p - __bfloat162float(phh));
                ls += p;
            }
            ls += __shfl_xor_sync(0xffffffffu, ls, 1);
            ls += __shfl_xor_sync(0xffffffffu, ls, 2);
            if (l4 == 0) { rmax[r] = nm; rsum[r] = rsum[r] * sc + ls; scl[r] = sc; }
        }
        __syncthreads();

        // [D] rescale acc, then acc += P*V (3-term split, V via ldmatrix.trans)
        {
            float s0 = scl[wm * 16 + grp];
            float s1 = scl[wm * 16 + grp + 8];
            #pragma unroll
            for (int nt = 0; nt < 4; nt++) {
                pacc[nt][0] *= s0; pacc[nt][1] *= s0;
                pacc[nt][2] *= s1; pacc[nt][3] *= s1;
            }
            int r = lane & 7, tt = lane >> 3;
            int lrow = wm * 16 + (lane & 15);
            int lcol8 = (lane >> 4) << 3;
            #pragma unroll
            for (int ks = 0; ks < 4; ks++) {
                unsigned ph_[4], pl_[4];
                unsigned ad = smem_u32(Ph + lrow * 72 + ks * 16 + lcol8);
                LDSM4(ph_[0], ph_[1], ph_[2], ph_[3], ad);
                LDSM4(pl_[0], pl_[1], pl_[2], pl_[3], ad + 9216u);
                unsigned vb[4][2], vl_[4][2];
                #pragma unroll
                for (int vp = 0; vp < 2; vp++) {
                    int vrow = ks * 16 + ((tt & 1) << 3) + r;
                    int ncol = wn * 32 + vp * 16 + ((tt >> 1) << 3);
                    unsigned vd = smem_u32(Vh + vrow * 72 + ncol);
                    unsigned r0, r1, r2, r3;
                    LDSM4T(r0, r1, r2, r3, vd);
                    vb[vp * 2][0] = r0; vb[vp * 2][1] = r1;
                    vb[vp * 2 + 1][0] = r2; vb[vp * 2 + 1][1] = r3;
                    LDSM4T(r0, r1, r2, r3, vd + 9216u);
                    vl_[vp * 2][0] = r0; vl_[vp * 2][1] = r1;
                    vl_[vp * 2 + 1][0] = r2; vl_[vp * 2 + 1][1] = r3;
                }
                #pragma unroll
                for (int nt = 0; nt < 4; nt++) {
                    MMA16816(pacc[nt], ph_, vb[nt]);
                    MMA16816(pacc[nt], ph_, vl_[nt]);
                    MMA16816(pacc[nt], pl_, vb[nt]);
                }
            }
        }
        __syncthreads();
    }

    // ---- normalize + raw-reshape scatter, emit bf16 hi/lo directly ----
    float inv0 = 1.f / rsum[wm * 16 + grp];
    float inv1 = 1.f / rsum[wm * 16 + grp + 8];
    #pragma unroll
    for (int half = 0; half < 2; half++) {
        int sg = qt * 64 + wm * 16 + grp + half * 8;     // query within branch
        int flat0 = h * (SPB_ * HD_) + sg * HD_;
        int sp = flat0 / C_;
        int tok = 1 + nb * SPB_ + sp;
        size_t obase = (size_t)(b * N_ + tok) * C_ + (flat0 - sp * C_);
        float inv = half ? inv1 : inv0;
        #pragma unroll
        for (int nt = 0; nt < 4; nt++) {
            int col = wn * 32 + nt * 8 + tq * 2;
            float v0 = pacc[nt][half * 2] * inv;
            float v1 = pacc[nt][half * 2 + 1] * inv;
            __nv_bfloat16 h0 = __float2bfloat16(v0);
            __nv_bfloat16 h1 = __float2bfloat16(v1);
            __nv_bfloat162 hp; hp.x = h0; hp.y = h1;
            __nv_bfloat162 lp;
            lp.x = __float2bfloat16(v0 - __bfloat162float(h0));
            lp.y = __float2bfloat16(v1 - __bfloat162float(h1));
            *(__nv_bfloat162*)(g_yh + obase + col) = hp;
            *(__nv_bfloat162*)(g_yl + obase + col) = lp;
        }
    }
}

// ---------------- launcher ----------------
extern "C" void kernel_launch(void* const* d_in, const int* in_sizes, int n_in,
                              void* d_out, int out_size) {
    const float* x      = (const float*)d_in[0];
    const float* ln1_w  = (const float*)d_in[1];
    const float* ln1_b  = (const float*)d_in[2];
    const float* qkv_w  = (const float*)d_in[3];
    const float* proj_w = (const float*)d_in[4];
    const float* proj_b = (const float*)d_in[5];
    const float* ln2_w  = (const float*)d_in[6];
    const float* ln2_b  = (const float*)d_in[7];
    const float* fc1_w  = (const float*)d_in[8];
    const float* fc1_b  = (const float*)d_in[9];
    const float* fc2_w  = (const float*)d_in[10];
    const float* fc2_b  = (const float*)d_in[11];
    float* out = (float*)d_out;

    cudaFuncSetAttribute(tc_qkv_kernel,  cudaFuncAttributeMaxDynamicSharedMemorySize, TC_SMEM);
    cudaFuncSetAttribute(tc_proj_kernel, cudaFuncAttributeMaxDynamicSharedMemorySize, TC_SMEM);
    cudaFuncSetAttribute(tc_fc1_kernel,  cudaFuncAttributeMaxDynamicSharedMemorySize, TC_SMEM);
    cudaFuncSetAttribute(tc_fc2_kernel,  cudaFuncAttributeMaxDynamicSharedMemorySize, TC_SMEM);
    cudaFuncSetAttribute(battn_tc_kernel, cudaFuncAttributeMaxDynamicSharedMemorySize, ATT_SMEM);

    dim3 blk(256);
    int mtiles = (M_ + 127) / 128;   // 129
    auto cgrid = [](int n) { return (n + 255) / 256; };

    __nv_bfloat16 *qwh, *qwl, *pwh, *pwl, *f1h, *f1l, *f2h, *f2l;
    cudaGetSymbolAddress((void**)&qwh, g_qwh);  cudaGetSymbolAddress((void**)&qwl, g_qwl);
    cudaGetSymbolAddress((void**)&pwh, g_pwh);  cudaGetSymbolAddress((void**)&pwl, g_pwl);
    cudaGetSymbolAddress((void**)&f1h, g_f1wh); cudaGetSymbolAddress((void**)&f1l, g_f1wl);
    cudaGetSymbolAddress((void**)&f2h, g_f2wh); cudaGetSymbolAddress((void**)&f2l, g_f2wl);

    // weight bf16 hi/lo splits (deterministic every call)
    conv_kernel<<<cgrid(QKVDIM_ * C_ / 4), blk>>>(qkv_w, qwh, qwl, QKVDIM_ * C_ / 4);
    conv_kernel<<<cgrid(C_ * C_ / 4), blk>>>(proj_w, pwh, pwl, C_ * C_ / 4);
    conv_kernel<<<cgrid(4 * C_ * C_ / 4), blk>>>(fc1_w, f1h, f1l, 4 * C_ * C_ / 4);
    conv_kernel<<<cgrid(4 * C_ * C_ / 4), blk>>>(fc2_w, f2h, f2l, 4 * C_ * C_ / 4);

    // 1. LN1 (fp32 + bf16 split)
    ln1_kernel<<<M_, blk>>>(x, ln1_w, ln1_b);
    // 2. qkv = hln @ qkv_w.T   (tensor cores)
    tc_qkv_kernel<<<dim3(QKVDIM_ / 128, mtiles), blk, TC_SMEM>>>();
    // 3. cls global attention -> g_cls, y row0 (bf16 split)
    cls_attn_kernel<<<B_ * H_, blk>>>();
    // 4. qkv of cls
    qkvc_kernel<<<dim3(QKVDIM_ / 256, B_), blk>>>(qkv_w);
    // 5. branch local attention (tensor cores) -> y rows 1.. (bf16 split)
    battn_tc_kernel<<<dim3(8, NB_, B_ * H_), blk, ATT_SMEM>>>();
    // 6. x1 = x + y @ proj_w.T + proj_b
    tc_proj_kernel<<<dim3(C_ / 128, mtiles), blk, TC_SMEM>>>(proj_b, x);
    // 7. LN2 (bf16 split out)
    ln2_kernel<<<M_, blk>>>(ln2_w, ln2_b);
    // 8. fc1 + exact gelu -> bf16 split
    tc_fc1_kernel<<<dim3(4 * C_ / 128, mtiles), blk, TC_SMEM>>>(fc1_b);
    // 9. out = x1 + gelu(fc1) @ fc2_w.T + fc2_b
    tc_fc2_kernel<<<dim3(C_ / 128, mtiles), blk, TC_SMEM>>>(fc2_b, out);
}